// round 8
// baseline (speedup 1.0000x reference)
#include <cuda_runtime.h>
#include <cuda_bf16.h>

#define B_  16
#define L_  2048
#define D_  256

// Scratch (layouts are mma-fragment-major; see converters):
//  g_Qfr : Q bf16 quads  [b][qtile128][kchunk16][lane32] (uint4, 16MB)
//  g_Kfr : K bf16 duos   [b][ntile256][kchunk16][lane32] (uint2, 16MB)
//  g_Vp  : V tf32-rounded, per (b,ktile32): [ks4][qd4][d256][p2] (33.5MB)
//  g_E   : exp(QK^T*scale) tf32-rounded, per (b,qpanel,ktile): [r16 8][ks4][lane32][4]
__device__ uint4  g_Qfr[(size_t)B_ * 128 * 16 * 32];
__device__ uint2  g_Kfr[(size_t)B_ * 256 * 16 * 32];
__device__ float  g_Vp[(size_t)B_ * L_ * D_];
__device__ float  g_E[(size_t)B_ * L_ * L_];
__device__ float  g_part[(size_t)B_ * L_ * 64];
__device__ float  g_inv[(size_t)B_ * L_];

__device__ __forceinline__ unsigned f2tf32(float x) {
    unsigned u;
    asm("cvt.rna.tf32.f32 %0, %1;" : "=r"(u) : "f"(x));
    return u;
}
__device__ __forceinline__ float f2tf32f(float x) { return __uint_as_float(f2tf32(x)); }

__device__ __forceinline__ unsigned pack_bf16x2(float lo, float hi) {
    unsigned r;
    asm("cvt.rn.bf16x2.f32 %0, %1, %2;" : "=r"(r) : "f"(hi), "f"(lo));
    return r;
}
__device__ __forceinline__ void mma_bf16(float* c, const unsigned* a, const unsigned* b) {
    asm volatile(
        "mma.sync.aligned.m16n8k16.row.col.f32.bf16.bf16.f32 "
        "{%0,%1,%2,%3}, {%4,%5,%6,%7}, {%8,%9}, {%0,%1,%2,%3};"
        : "+f"(c[0]), "+f"(c[1]), "+f"(c[2]), "+f"(c[3])
        : "r"(a[0]), "r"(a[1]), "r"(a[2]), "r"(a[3]), "r"(b[0]), "r"(b[1]));
}
__device__ __forceinline__ void mma_tf32(float* c, const unsigned* a, const unsigned* b) {
    asm volatile(
        "mma.sync.aligned.m16n8k8.row.col.f32.tf32.tf32.f32 "
        "{%0,%1,%2,%3}, {%4,%5,%6,%7}, {%8,%9}, {%0,%1,%2,%3};"
        : "+f"(c[0]), "+f"(c[1]), "+f"(c[2]), "+f"(c[3])
        : "r"(a[0]), "r"(a[1]), "r"(a[2]), "r"(a[3]), "r"(b[0]), "r"(b[1]));
}
__device__ __forceinline__ void cp_async16(unsigned dst, const void* src) {
    asm volatile("cp.async.cg.shared.global [%0], [%1], 16;" :: "r"(dst), "l"(src));
}
#define CP_COMMIT() asm volatile("cp.async.commit_group;" ::: "memory")
#define CP_WAIT1()  asm volatile("cp.async.wait_group 1;" ::: "memory")

// ---------------------------------------------------------------------------
// Converter A: Q -> bf16 fragment quads. One 16B quad per thread (coalesced).
// quad(b,qtile,kchunk,lane): lane=(g,qd); words a0..a3 =
//   (row g,  k 2qd..2qd+1), (g+8, same), (g, 2qd+8..9), (g+8, 2qd+8..9)
// ---------------------------------------------------------------------------
__global__ void cvt_q_kernel(const float* __restrict__ Q) {
    const int j = blockIdx.x * 256 + threadIdx.x;
    const int lane = j & 31, kc = (j >> 5) & 15, qt = (j >> 9) & 127, b = j >> 16;
    const int g = lane >> 2, qd = lane & 3;
    const float* base = Q + ((size_t)(b * L_) + qt * 16) * D_ + kc * 16 + qd * 2;
    const float2 r0a = *(const float2*)(base + (size_t)g * D_);
    const float2 r0b = *(const float2*)(base + (size_t)g * D_ + 8);
    const float2 r1a = *(const float2*)(base + (size_t)(g + 8) * D_);
    const float2 r1b = *(const float2*)(base + (size_t)(g + 8) * D_ + 8);
    uint4 out;
    out.x = pack_bf16x2(r0a.x, r0a.y);
    out.y = pack_bf16x2(r1a.x, r1a.y);
    out.z = pack_bf16x2(r0b.x, r0b.y);
    out.w = pack_bf16x2(r1b.x, r1b.y);
    g_Qfr[j] = out;
}

// ---------------------------------------------------------------------------
// Converter B: K -> bf16 fragment duos. One 8B duo per thread (coalesced).
// duo(b,ntile,kchunk,lane): (row g, k 2qd..2qd+1), (row g, 2qd+8..9)
// ---------------------------------------------------------------------------
__global__ void cvt_k_kernel(const float* __restrict__ K) {
    const int j = blockIdx.x * 256 + threadIdx.x;
    const int lane = j & 31, kc = (j >> 5) & 15, nt = (j >> 9) & 255, b = j >> 17;
    const int g = lane >> 2, qd = lane & 3;
    const float* base = K + ((size_t)(b * L_) + nt * 8 + g) * D_ + kc * 16 + qd * 2;
    const float2 a = *(const float2*)(base);
    const float2 c = *(const float2*)(base + 8);
    uint2 out;
    out.x = pack_bf16x2(a.x, a.y);
    out.y = pack_bf16x2(c.x, c.y);
    g_Kfr[j] = out;
}

// ---------------------------------------------------------------------------
// Converter C: V -> tf32-rounded permuted layout (as R7).
// ---------------------------------------------------------------------------
__global__ void cvt_v_kernel(const float* __restrict__ V) {
    const size_t i = (size_t)blockIdx.x * blockDim.x + threadIdx.x;
    const float4 v = ((const float4*)V)[i];
    const size_t i4 = i * 4;
    const int d   = (int)(i4 & (D_ - 1));
    const int kr  = (int)((i4 >> 8) & (L_ - 1));
    const int bb_ = (int)(i4 >> 19);
    const int ktile = kr >> 5, kk = kr & 31;
    const int ks = kk >> 3, p = (kk >> 2) & 1, qd = kk & 3;
    float* dst = g_Vp + ((size_t)(bb_ * 64 + ktile)) * 8192
                      + (size_t)((ks * 4 + qd) * 256) * 2 + p;
    dst[(d + 0) * 2] = f2tf32f(v.x);
    dst[(d + 1) * 2] = f2tf32f(v.y);
    dst[(d + 2) * 2] = f2tf32f(v.z);
    dst[(d + 3) * 2] = f2tf32f(v.w);
}

// ---------------------------------------------------------------------------
// Kernel 1: E = tf32(exp(scale * Q K^T)) in av-quad layout + partial row sums.
// Fragment-major smem: A-frag = 1 LDS.128, B-frag = 1 LDS.64. Conflict-free.
// ---------------------------------------------------------------------------
#define QK_STAGE_U 4096    // u32 per stage: Q 2048 + K 2048

__global__ __launch_bounds__(256, 2)
void qk_exp_kernel(float* __restrict__ E_out,
                   const int* __restrict__ if_draw) {
    extern __shared__ unsigned smem_u[];
    const unsigned sbase = (unsigned)__cvta_generic_to_shared(smem_u);

    const int b  = blockIdx.z;
    const int by = blockIdx.y;
    const int kx = blockIdx.x;
    const int q0 = by * 128;
    const int k0 = kx * 128;

    const int tid  = threadIdx.x;
    const int lane = tid & 31;
    const int wid  = tid >> 5;
    const int wmid = wid & 1;          // m half (64 rows)
    const int wnid = wid >> 1;         // n quarter (32 cols)
    const int g    = lane >> 2;
    const int qd   = lane & 3;

    float acc[4][4][4] = {};

    auto load_stage = [&](int ss, int kt16) {
        const unsigned qdst = sbase + (unsigned)ss * QK_STAGE_U * 4;
        const unsigned kdst = qdst + 2048 * 4;
        #pragma unroll
        for (int t = 0; t < 2; t++) {
            const int idx = tid + t * 256;
            {   // Q: 512 x 16B
                const int qtl = idx >> 6, rem = idx & 63;
                const uint4* src = g_Qfr + ((size_t)(b * 128 + (q0 >> 4) + qtl) * 512
                                            + kt16 * 32 + rem);
                cp_async16(qdst + (unsigned)idx * 16, src);
            }
            {   // K: 512 x 16B
                const int ntl = idx >> 5, rem = idx & 31;
                const uint2* src = g_Kfr + ((size_t)(b * 256 + (k0 >> 3) + ntl) * 512
                                            + kt16 * 32 + rem * 2);
                cp_async16(kdst + (unsigned)idx * 16, src);
            }
        }
    };

    load_stage(0, 0); CP_COMMIT();
    load_stage(1, 2); CP_COMMIT();

    for (int i = 0; i < 8; i++) {
        CP_WAIT1();
        __syncthreads();
        if (i + 2 < 8) load_stage((i + 2) % 3, (i + 2) * 2);
        CP_COMMIT();

        const unsigned* Qst = smem_u + (i % 3) * QK_STAGE_U;
        const unsigned* Kst = Qst + 2048;

        #pragma unroll
        for (int ks = 0; ks < 2; ks++) {
            unsigned a[4][4], bb[4][2];
            #pragma unroll
            for (int mt = 0; mt < 4; mt++) {
                const uint4 q4 = *(const uint4*)(Qst + ((wmid * 4 + mt) * 2 + ks) * 128 + lane * 4);
                a[mt][0] = q4.x; a[mt][1] = q4.y; a[mt][2] = q4.z; a[mt][3] = q4.w;
            }
            #pragma unroll
            for (int nt = 0; nt < 4; nt++) {
                const uint2 k2 = *(const uint2*)(Kst + ((wnid * 4 + nt) * 2 + ks) * 64 + lane * 2);
                bb[nt][0] = k2.x; bb[nt][1] = k2.y;
            }
            #pragma unroll
            for (int mt = 0; mt < 4; mt++)
                #pragma unroll
                for (int nt = 0; nt < 4; nt++)
                    mma_bf16(acc[mt][nt], a[mt], bb[nt]);
        }
    }

    // Epilogue: exp (fast), tf32-round, store E quads, partial row sums.
    const float scale = (if_draw[0] != 0) ? (1.0f / 320.0f) : (1.0f / 16.0f);
    float* Eq = E_out + ((size_t)(b * 16 + by) * 64 + (size_t)kx * 4 + wnid) * 4096;
    const int qdp  = (2 * qd) & 3;     // quad qd'
    const int hoff = (qd >> 1) * 2;    // slot offset from half

    #pragma unroll
    for (int mt = 0; mt < 4; mt++) {
        float slo = 0.f, shi = 0.f;
        const int r16 = wmid * 4 + mt;
        #pragma unroll
        for (int nt = 0; nt < 4; nt++) {
            float e0 = f2tf32f(__expf(scale * acc[mt][nt][0]));
            float e1 = f2tf32f(__expf(scale * acc[mt][nt][1]));
            float e2 = f2tf32f(__expf(scale * acc[mt][nt][2]));
            float e3 = f2tf32f(__expf(scale * acc[mt][nt][3]));
            slo += e0 + e1;
            shi += e2 + e3;
            const int off = r16 * 512 + nt * 128 + (g * 4 + qdp) * 4 + hoff;
            float2 p0 = {e0, e2};   // rows (g, g+8) at col c
            float2 p1 = {e1, e3};   // rows (g, g+8) at col c+1
            *(float2*)(Eq + off)     = p0;
            *(float2*)(Eq + off + 4) = p1;
        }
        slo += __shfl_xor_sync(0xffffffffu, slo, 1);
        slo += __shfl_xor_sync(0xffffffffu, slo, 2);
        shi += __shfl_xor_sync(0xffffffffu, shi, 1);
        shi += __shfl_xor_sync(0xffffffffu, shi, 2);
        if (qd == 0) {
            const size_t rbase = (size_t)(b * L_ + q0 + wmid * 64 + mt * 16 + g) * 64 + kx * 4 + wnid;
            g_part[rbase]          = slo;
            g_part[rbase + 8 * 64] = shi;   // row+8
        }
    }
}

// ---------------------------------------------------------------------------
// Kernel 1b: reduce 64 partials per row -> g_inv = 1/rowsum.
// ---------------------------------------------------------------------------
__global__ void rowinv_kernel() {
    const int row  = blockIdx.x * 8 + (threadIdx.x >> 5);
    const int lane = threadIdx.x & 31;
    const float* p = g_part + (size_t)row * 64;
    float s = p[lane] + p[lane + 32];
    #pragma unroll
    for (int o = 16; o > 0; o >>= 1)
        s += __shfl_xor_sync(0xffffffffu, s, o);
    if (lane == 0) g_inv[row] = 1.0f / s;
}

// ---------------------------------------------------------------------------
// Kernel 2: O = (E @ V) * inv ; attn = E * inv (d0==0 blocks).
// A-frag = 1 LDS.128 from E quads; V-frag = 1 LDS.64. Conflict-free.
// ---------------------------------------------------------------------------
#define AV_A_F     4096
#define AV_STAGE_F 8320    // A 4096 + V 4224 (16 rows x 264 padded)

__global__ __launch_bounds__(256, 2)
void av_fused_kernel(float* __restrict__ O,
                     float* __restrict__ attn) {
    extern __shared__ float smem_f[];
    const unsigned sbase = (unsigned)__cvta_generic_to_shared(smem_f);
    float* inv_s = smem_f + 3 * AV_STAGE_F;

    const int b  = blockIdx.z;
    const int q0 = blockIdx.y * 128;
    const int d0 = blockIdx.x * 128;
    const bool wr_attn = (blockIdx.x == 0);

    const float* Ab = g_E  + ((size_t)(b * 16 + blockIdx.y) * 64) * 4096;
    const float* Vb = g_Vp + (size_t)b * 64 * 8192;

    const int tid  = threadIdx.x;
    const int lane = tid & 31;
    const int wid  = tid >> 5;
    const int wm16 = (wid & 1) * 4;
    const int wn   = (wid >> 1) * 32;
    const int g    = lane >> 2;
    const int qd   = lane & 3;

    float acc[4][4][4] = {};

    if (tid < 128) inv_s[tid] = g_inv[b * L_ + q0 + tid];

    auto load_stage = [&](int ss, int ktile) {
        const unsigned adst = sbase + (unsigned)ss * AV_STAGE_F * 4;
        const unsigned vdst = adst + AV_A_F * 4;
        const float* Agm = Ab + (size_t)ktile * 4096;
        const float* Vgm = Vb + (size_t)ktile * 8192 + d0 * 2;
        #pragma unroll
        for (int t = 0; t < 4; t++) {
            const int idx = tid + t * 256;
            cp_async16(adst + (unsigned)idx * 16, Agm + idx * 4);
            const int vrow = idx >> 6, vrem = (idx & 63) * 4;
            cp_async16(vdst + (unsigned)(vrow * 264 + vrem) * 4, Vgm + vrow * 512 + vrem);
        }
    };

    load_stage(0, 0); CP_COMMIT();
    load_stage(1, 1); CP_COMMIT();

    float* attn_b = attn + (size_t)b * L_ * L_;

    for (int i = 0; i < 64; i++) {
        CP_WAIT1();
        __syncthreads();
        if (i + 2 < 64) load_stage((i + 2) % 3, i + 2);
        CP_COMMIT();

        const float* Ast = smem_f + (i % 3) * AV_STAGE_F;
        const float* Vst = Ast + AV_A_F;

        // attn = E * inv straight from staged quads.
        if (wr_attn) {
            #pragma unroll
            for (int t = 0; t < 4; t++) {
                const int id = tid + t * 256;          // 1024 quads
                const int r16 = id >> 7, ks = (id >> 5) & 3, q = id & 31;
                const int gg = q >> 2, qq = q & 3;
                const float4 e = *(const float4*)(Ast + id * 4);
                const int lr0 = r16 * 16 + gg, lr1 = lr0 + 8;
                const float iv0 = inv_s[lr0], iv1 = inv_s[lr1];
                float* row0 = attn_b + (size_t)(q0 + lr0) * L_ + i * 32 + ks * 8 + qq;
                float* row1 = attn_b + (size_t)(q0 + lr1) * L_ + i * 32 + ks * 8 + qq;
                row0[0] = e.x * iv0;
                row1[0] = e.y * iv1;
                row0[4] = e.z * iv0;
                row1[4] = e.w * iv1;
            }
        }

        #pragma unroll
        for (int ks = 0; ks < 4; ks++) {
            unsigned a[4][4], bb[4][2];
            #pragma unroll
            for (int mt = 0; mt < 4; mt++) {
                const uint4 q4 = *(const uint4*)(Ast + (wm16 + mt) * 512 + ks * 128 + lane * 4);
                a[mt][0] = q4.x; a[mt][1] = q4.y; a[mt][2] = q4.z; a[mt][3] = q4.w;
            }
            #pragma unroll
            for (int nt = 0; nt < 4; nt++) {
                const int nc = wn + nt * 8 + g;
                const float2 v01 = *(const float2*)(Vst + (ks * 4 + qd) * 264 + nc * 2);
                bb[nt][0] = __float_as_uint(v01.x);
                bb[nt][1] = __float_as_uint(v01.y);
            }
            #pragma unroll
            for (int mt = 0; mt < 4; mt++)
                #pragma unroll
                for (int nt = 0; nt < 4; nt++)
                    mma_tf32(acc[mt][nt], a[mt], bb[nt]);
        }
    }

    float* Ob = O + (size_t)b * L_ * D_;
    #pragma unroll
    for (int mt = 0; mt < 4; mt++) {
        const int lrow = (wid & 1) * 64 + mt * 16 + g;
        const int row  = q0 + lrow;
        const float iv0 = inv_s[lrow];
        const float iv1 = inv_s[lrow + 8];
        #pragma unroll
        for (int nt = 0; nt < 4; nt++) {
            const int col = d0 + wn + nt * 8 + 2 * qd;
            float2 v0 = {acc[mt][nt][0] * iv0, acc[mt][nt][1] * iv0};
            float2 v1 = {acc[mt][nt][2] * iv1, acc[mt][nt][3] * iv1};
            *(float2*)(Ob + (size_t)row * D_ + col)       = v0;
            *(float2*)(Ob + (size_t)(row + 8) * D_ + col) = v1;
        }
    }
}

// ---------------------------------------------------------------------------
// Launch
// ---------------------------------------------------------------------------
extern "C" void kernel_launch(void* const* d_in, const int* in_sizes, int n_in,
                              void* d_out, int out_size) {
    const float* Q = (const float*)d_in[0];
    const float* K = (const float*)d_in[1];
    const float* V = (const float*)d_in[2];
    const int* if_draw = (const int*)d_in[4];

    float* out = (float*)d_out;

    const long long ctx_elems  = (long long)B_ * L_ * D_;
    const long long attn_elems = (long long)B_ * L_ * L_;

    float* Sptr;
    if ((long long)out_size >= ctx_elems + attn_elems)
        Sptr = out + ((long long)out_size - attn_elems);
    else
        Sptr = out + ctx_elems;

    static int attr_done = 0;
    const int qk_smem = QK_STAGE_U * 3 * 4;          // 49152 B
    const int av_smem = AV_STAGE_F * 3 * 4 + 512;    // 100352 B
    if (!attr_done) {
        cudaFuncSetAttribute(qk_exp_kernel, cudaFuncAttributeMaxDynamicSharedMemorySize, qk_smem);
        cudaFuncSetAttribute(av_fused_kernel, cudaFuncAttributeMaxDynamicSharedMemorySize, av_smem);
        attr_done = 1;
    }

    float* Eptr;
    cudaGetSymbolAddress((void**)&Eptr, g_E);

    cvt_q_kernel<<<(B_ * 128 * 16 * 32) / 256, 256>>>(Q);
    cvt_k_kernel<<<(B_ * 256 * 16 * 32) / 256, 256>>>(K);
    cvt_v_kernel<<<(B_ * L_ * D_ / 4) / 256, 256>>>(V);

    dim3 g1(L_ / 128, L_ / 128, B_);    // (16, 16, 16)
    qk_exp_kernel<<<g1, 256, qk_smem>>>(Eptr, if_draw);

    rowinv_kernel<<<(B_ * L_) / 8, 256>>>();

    dim3 g2(D_ / 128, L_ / 128, B_);    // (2, 16, 16)
    av_fused_kernel<<<g2, 256, av_smem>>>(out, Sptr);
}

// round 9
// speedup vs baseline: 1.1213x; 1.1213x over previous
#include <cuda_runtime.h>
#include <cuda_bf16.h>

#define B_  16
#define L_  2048
#define D_  256

// Scratch (mma-fragment-major layouts; see converters):
//  g_Qfr : Q bf16 quads  [b][qtile128][kchunk16][lane32] (uint4)
//  g_Kfr : K bf16 duos   [b][ntile256][kchunk16][lane32] (uint2)
//  g_Vp  : V tf32-rounded, per (b,ktile32): [ks4][qd4][d256][p2]
//  g_E   : exp(QK^T*scale) tf32-rounded quads, per (b,qpanel,ktile): [r16 8][ks4][lane32][4]
__device__ uint4  g_Qfr[(size_t)B_ * 128 * 16 * 32];
__device__ uint2  g_Kfr[(size_t)B_ * 256 * 16 * 32];
__device__ float  g_Vp[(size_t)B_ * L_ * D_];
__device__ float  g_E[(size_t)B_ * L_ * L_];
__device__ float  g_part[(size_t)B_ * L_ * 64];
__device__ float  g_inv[(size_t)B_ * L_];

__device__ __forceinline__ unsigned f2tf32(float x) {
    unsigned u;
    asm("cvt.rna.tf32.f32 %0, %1;" : "=r"(u) : "f"(x));
    return u;
}
__device__ __forceinline__ float f2tf32f(float x) { return __uint_as_float(f2tf32(x)); }

__device__ __forceinline__ unsigned pack_bf16x2(float lo, float hi) {
    unsigned r;
    asm("cvt.rn.bf16x2.f32 %0, %1, %2;" : "=r"(r) : "f"(hi), "f"(lo));
    return r;
}
__device__ __forceinline__ void mma_bf16(float* c, const unsigned* a, const unsigned* b) {
    asm volatile(
        "mma.sync.aligned.m16n8k16.row.col.f32.bf16.bf16.f32 "
        "{%0,%1,%2,%3}, {%4,%5,%6,%7}, {%8,%9}, {%0,%1,%2,%3};"
        : "+f"(c[0]), "+f"(c[1]), "+f"(c[2]), "+f"(c[3])
        : "r"(a[0]), "r"(a[1]), "r"(a[2]), "r"(a[3]), "r"(b[0]), "r"(b[1]));
}
__device__ __forceinline__ void mma_tf32(float* c, const unsigned* a, const unsigned* b) {
    asm volatile(
        "mma.sync.aligned.m16n8k8.row.col.f32.tf32.tf32.f32 "
        "{%0,%1,%2,%3}, {%4,%5,%6,%7}, {%8,%9}, {%0,%1,%2,%3};"
        : "+f"(c[0]), "+f"(c[1]), "+f"(c[2]), "+f"(c[3])
        : "r"(a[0]), "r"(a[1]), "r"(a[2]), "r"(a[3]), "r"(b[0]), "r"(b[1]));
}
__device__ __forceinline__ void cp_async16(unsigned dst, const void* src) {
    asm volatile("cp.async.cg.shared.global [%0], [%1], 16;" :: "r"(dst), "l"(src));
}
#define CP_COMMIT() asm volatile("cp.async.commit_group;" ::: "memory")
#define CP_WAIT1()  asm volatile("cp.async.wait_group 1;" ::: "memory")

// ---------------------------------------------------------------------------
// Converter A: Q -> bf16 fragment quads (one 16B quad per thread, coalesced).
// ---------------------------------------------------------------------------
__global__ void cvt_q_kernel(const float* __restrict__ Q) {
    const int j = blockIdx.x * 256 + threadIdx.x;
    const int lane = j & 31, kc = (j >> 5) & 15, qt = (j >> 9) & 127, b = j >> 16;
    const int g = lane >> 2, qd = lane & 3;
    const float* base = Q + ((size_t)(b * L_) + qt * 16) * D_ + kc * 16 + qd * 2;
    const float2 r0a = *(const float2*)(base + (size_t)g * D_);
    const float2 r0b = *(const float2*)(base + (size_t)g * D_ + 8);
    const float2 r1a = *(const float2*)(base + (size_t)(g + 8) * D_);
    const float2 r1b = *(const float2*)(base + (size_t)(g + 8) * D_ + 8);
    uint4 out;
    out.x = pack_bf16x2(r0a.x, r0a.y);
    out.y = pack_bf16x2(r1a.x, r1a.y);
    out.z = pack_bf16x2(r0b.x, r0b.y);
    out.w = pack_bf16x2(r1b.x, r1b.y);
    g_Qfr[j] = out;
}

// ---------------------------------------------------------------------------
// Converter B: K -> bf16 fragment duos (one 8B duo per thread, coalesced).
// ---------------------------------------------------------------------------
__global__ void cvt_k_kernel(const float* __restrict__ K) {
    const int j = blockIdx.x * 256 + threadIdx.x;
    const int lane = j & 31, kc = (j >> 5) & 15, nt = (j >> 9) & 255, b = j >> 17;
    const int g = lane >> 2, qd = lane & 3;
    const float* base = K + ((size_t)(b * L_) + nt * 8 + g) * D_ + kc * 16 + qd * 2;
    const float2 a = *(const float2*)(base);
    const float2 c = *(const float2*)(base + 8);
    uint2 out;
    out.x = pack_bf16x2(a.x, a.y);
    out.y = pack_bf16x2(c.x, c.y);
    g_Kfr[j] = out;
}

// ---------------------------------------------------------------------------
// Converter C: V -> tf32-rounded permuted layout.
// ---------------------------------------------------------------------------
__global__ void cvt_v_kernel(const float* __restrict__ V) {
    const size_t i = (size_t)blockIdx.x * blockDim.x + threadIdx.x;
    const float4 v = ((const float4*)V)[i];
    const size_t i4 = i * 4;
    const int d   = (int)(i4 & (D_ - 1));
    const int kr  = (int)((i4 >> 8) & (L_ - 1));
    const int bb_ = (int)(i4 >> 19);
    const int ktile = kr >> 5, kk = kr & 31;
    const int ks = kk >> 3, p = (kk >> 2) & 1, qd = kk & 3;
    float* dst = g_Vp + ((size_t)(bb_ * 64 + ktile)) * 8192
                      + (size_t)((ks * 4 + qd) * 256) * 2 + p;
    dst[(d + 0) * 2] = f2tf32f(v.x);
    dst[(d + 1) * 2] = f2tf32f(v.y);
    dst[(d + 2) * 2] = f2tf32f(v.z);
    dst[(d + 3) * 2] = f2tf32f(v.w);
}

// ---------------------------------------------------------------------------
// Kernel 1: E = tf32(exp(scale * Q K^T)) quads + partial row sums.
// A-frag = 1 LDS.128, B-frag = 1 LDS.64. Conflict-free.
// ---------------------------------------------------------------------------
#define QK_STAGE_U 4096

__global__ __launch_bounds__(256, 2)
void qk_exp_kernel(float* __restrict__ E_out,
                   const int* __restrict__ if_draw) {
    extern __shared__ unsigned smem_u[];
    const unsigned sbase = (unsigned)__cvta_generic_to_shared(smem_u);

    const int b  = blockIdx.z;
    const int by = blockIdx.y;
    const int kx = blockIdx.x;
    const int q0 = by * 128;
    const int k0 = kx * 128;

    const int tid  = threadIdx.x;
    const int lane = tid & 31;
    const int wid  = tid >> 5;
    const int wmid = wid & 1;
    const int wnid = wid >> 1;
    const int g    = lane >> 2;
    const int qd   = lane & 3;

    float acc[4][4][4] = {};

    auto load_stage = [&](int ss, int kt16) {
        const unsigned qdst = sbase + (unsigned)ss * QK_STAGE_U * 4;
        const unsigned kdst = qdst + 2048 * 4;
        #pragma unroll
        for (int t = 0; t < 2; t++) {
            const int idx = tid + t * 256;
            {
                const int qtl = idx >> 6, rem = idx & 63;
                const uint4* src = g_Qfr + ((size_t)(b * 128 + (q0 >> 4) + qtl) * 512
                                            + kt16 * 32 + rem);
                cp_async16(qdst + (unsigned)idx * 16, src);
            }
            {
                const int ntl = idx >> 5, rem = idx & 31;
                const uint2* src = g_Kfr + ((size_t)(b * 256 + (k0 >> 3) + ntl) * 512
                                            + kt16 * 32 + rem * 2);
                cp_async16(kdst + (unsigned)idx * 16, src);
            }
        }
    };

    load_stage(0, 0); CP_COMMIT();
    load_stage(1, 2); CP_COMMIT();

    for (int i = 0; i < 8; i++) {
        CP_WAIT1();
        __syncthreads();
        if (i + 2 < 8) load_stage((i + 2) % 3, (i + 2) * 2);
        CP_COMMIT();

        const unsigned* Qst = smem_u + (i % 3) * QK_STAGE_U;
        const unsigned* Kst = Qst + 2048;

        #pragma unroll
        for (int ks = 0; ks < 2; ks++) {
            unsigned a[4][4], bb[4][2];
            #pragma unroll
            for (int mt = 0; mt < 4; mt++) {
                const uint4 q4 = *(const uint4*)(Qst + ((wmid * 4 + mt) * 2 + ks) * 128 + lane * 4);
                a[mt][0] = q4.x; a[mt][1] = q4.y; a[mt][2] = q4.z; a[mt][3] = q4.w;
            }
            #pragma unroll
            for (int nt = 0; nt < 4; nt++) {
                const uint2 k2 = *(const uint2*)(Kst + ((wnid * 4 + nt) * 2 + ks) * 64 + lane * 2);
                bb[nt][0] = k2.x; bb[nt][1] = k2.y;
            }
            #pragma unroll
            for (int mt = 0; mt < 4; mt++)
                #pragma unroll
                for (int nt = 0; nt < 4; nt++)
                    mma_bf16(acc[mt][nt], a[mt], bb[nt]);
        }
    }

    const float scale = (if_draw[0] != 0) ? (1.0f / 320.0f) : (1.0f / 16.0f);
    float* Eq = E_out + ((size_t)(b * 16 + by) * 64 + (size_t)kx * 4 + wnid) * 4096;
    const int qdp  = (2 * qd) & 3;
    const int hoff = (qd >> 1) * 2;

    #pragma unroll
    for (int mt = 0; mt < 4; mt++) {
        float slo = 0.f, shi = 0.f;
        const int r16 = wmid * 4 + mt;
        #pragma unroll
        for (int nt = 0; nt < 4; nt++) {
            float e0 = f2tf32f(__expf(scale * acc[mt][nt][0]));
            float e1 = f2tf32f(__expf(scale * acc[mt][nt][1]));
            float e2 = f2tf32f(__expf(scale * acc[mt][nt][2]));
            float e3 = f2tf32f(__expf(scale * acc[mt][nt][3]));
            slo += e0 + e1;
            shi += e2 + e3;
            const int off = r16 * 512 + nt * 128 + (g * 4 + qdp) * 4 + hoff;
            float2 p0 = {e0, e2};
            float2 p1 = {e1, e3};
            *(float2*)(Eq + off)     = p0;
            *(float2*)(Eq + off + 4) = p1;
        }
        slo += __shfl_xor_sync(0xffffffffu, slo, 1);
        slo += __shfl_xor_sync(0xffffffffu, slo, 2);
        shi += __shfl_xor_sync(0xffffffffu, shi, 1);
        shi += __shfl_xor_sync(0xffffffffu, shi, 2);
        if (qd == 0) {
            const size_t rbase = (size_t)(b * L_ + q0 + wmid * 64 + mt * 16 + g) * 64 + kx * 4 + wnid;
            g_part[rbase]          = slo;
            g_part[rbase + 8 * 64] = shi;
        }
    }
}

// ---------------------------------------------------------------------------
// Kernel 1b: reduce 64 partials per row -> g_inv = 1/rowsum.
// ---------------------------------------------------------------------------
__global__ void rowinv_kernel() {
    const int row  = blockIdx.x * 8 + (threadIdx.x >> 5);
    const int lane = threadIdx.x & 31;
    const float* p = g_part + (size_t)row * 64;
    float s = p[lane] + p[lane + 32];
    #pragma unroll
    for (int o = 16; o > 0; o >>= 1)
        s += __shfl_xor_sync(0xffffffffu, s, o);
    if (lane == 0) g_inv[row] = 1.0f / s;
}

// ---------------------------------------------------------------------------
// Kernel 2: O = (E @ V) * inv ; attn = E * inv.
// attn write: coalesced per-row stores via quad-pair decode
//   col(m) = (m>>1) + (m&1)*4 inside each 8-col group.
// attn-writing alternates between the two d-blocks by iteration parity.
// ---------------------------------------------------------------------------
#define AV_A_F     4096
#define AV_STAGE_F 8320

__global__ __launch_bounds__(256, 2)
void av_fused_kernel(float* __restrict__ O,
                     float* __restrict__ attn) {
    extern __shared__ float smem_f[];
    const unsigned sbase = (unsigned)__cvta_generic_to_shared(smem_f);
    float* inv_s = smem_f + 3 * AV_STAGE_F;

    const int b  = blockIdx.z;
    const int q0 = blockIdx.y * 128;
    const int d0 = blockIdx.x * 128;
    const int my_par = blockIdx.x;      // attn-write parity owner

    const float* Ab = g_E  + ((size_t)(b * 16 + blockIdx.y) * 64) * 4096;
    const float* Vb = g_Vp + (size_t)b * 64 * 8192;

    const int tid  = threadIdx.x;
    const int lane = tid & 31;
    const int wid  = tid >> 5;
    const int wm16 = (wid & 1) * 4;
    const int wn   = (wid >> 1) * 32;
    const int g    = lane >> 2;
    const int qd   = lane & 3;

    // attn-write decode (per-lane constants)
    const int ntk = lane >> 3;
    const int m   = lane & 7;
    const int cw  = (m >> 1) + (m & 1) * 4;   // permuted col within 8-group

    float acc[4][4][4] = {};

    if (tid < 128) inv_s[tid] = g_inv[b * L_ + q0 + tid];

    auto load_stage = [&](int ss, int ktile) {
        const unsigned adst = sbase + (unsigned)ss * AV_STAGE_F * 4;
        const unsigned vdst = adst + AV_A_F * 4;
        const float* Agm = Ab + (size_t)ktile * 4096;
        const float* Vgm = Vb + (size_t)ktile * 8192 + d0 * 2;
        #pragma unroll
        for (int t = 0; t < 4; t++) {
            const int idx = tid + t * 256;
            cp_async16(adst + (unsigned)idx * 16, Agm + idx * 4);
            const int vrow = idx >> 6, vrem = (idx & 63) * 4;
            cp_async16(vdst + (unsigned)(vrow * 264 + vrem) * 4, Vgm + vrow * 512 + vrem);
        }
    };

    load_stage(0, 0); CP_COMMIT();
    load_stage(1, 1); CP_COMMIT();

    float* attn_b = attn + (size_t)b * L_ * L_;

    for (int i = 0; i < 64; i++) {
        CP_WAIT1();
        __syncthreads();
        if (i + 2 < 64) load_stage((i + 2) % 3, i + 2);
        CP_COMMIT();

        const float* Ast = smem_f + (i % 3) * AV_STAGE_F;
        const float* Vst = Ast + AV_A_F;

        // attn = E * inv — coalesced row stores; split by iteration parity.
        if ((i & 1) == my_par) {
            #pragma unroll
            for (int t = 0; t < 8; t++) {
                const int grp = wid * 8 + t;       // 0..63 = (r16, gg)
                const int r16 = grp >> 3, gg = grp & 7;
                const float2 e = *(const float2*)(Ast + r16 * 512 + ntk * 128 + gg * 16 + m * 2);
                const int lr0 = r16 * 16 + gg;
                const int col = i * 32 + ntk * 8 + cw;
                attn_b[(size_t)(q0 + lr0) * L_ + col]     = e.x * inv_s[lr0];
                attn_b[(size_t)(q0 + lr0 + 8) * L_ + col] = e.y * inv_s[lr0 + 8];
            }
        }

        #pragma unroll
        for (int ks = 0; ks < 4; ks++) {
            unsigned a[4][4], bb[4][2];
            #pragma unroll
            for (int mt = 0; mt < 4; mt++) {
                const uint4 q4 = *(const uint4*)(Ast + (wm16 + mt) * 512 + ks * 128 + lane * 4);
                a[mt][0] = q4.x; a[mt][1] = q4.y; a[mt][2] = q4.z; a[mt][3] = q4.w;
            }
            #pragma unroll
            for (int nt = 0; nt < 4; nt++) {
                const int nc = wn + nt * 8 + g;
                const float2 v01 = *(const float2*)(Vst + (ks * 4 + qd) * 264 + nc * 2);
                bb[nt][0] = __float_as_uint(v01.x);
                bb[nt][1] = __float_as_uint(v01.y);
            }
            #pragma unroll
            for (int mt = 0; mt < 4; mt++)
                #pragma unroll
                for (int nt = 0; nt < 4; nt++)
                    mma_tf32(acc[mt][nt], a[mt], bb[nt]);
        }
    }

    float* Ob = O + (size_t)b * L_ * D_;
    #pragma unroll
    for (int mt = 0; mt < 4; mt++) {
        const int lrow = (wid & 1) * 64 + mt * 16 + g;
        const int row  = q0 + lrow;
        const float iv0 = inv_s[lrow];
        const float iv1 = inv_s[lrow + 8];
        #pragma unroll
        for (int nt = 0; nt < 4; nt++) {
            const int col = d0 + wn + nt * 8 + 2 * qd;
            float2 v0 = {acc[mt][nt][0] * iv0, acc[mt][nt][1] * iv0};
            float2 v1 = {acc[mt][nt][2] * iv1, acc[mt][nt][3] * iv1};
            *(float2*)(Ob + (size_t)row * D_ + col)       = v0;
            *(float2*)(Ob + (size_t)(row + 8) * D_ + col) = v1;
        }
    }
}

// ---------------------------------------------------------------------------
// Launch
// ---------------------------------------------------------------------------
extern "C" void kernel_launch(void* const* d_in, const int* in_sizes, int n_in,
                              void* d_out, int out_size) {
    const float* Q = (const float*)d_in[0];
    const float* K = (const float*)d_in[1];
    const float* V = (const float*)d_in[2];
    const int* if_draw = (const int*)d_in[4];

    float* out = (float*)d_out;

    const long long ctx_elems  = (long long)B_ * L_ * D_;
    const long long attn_elems = (long long)B_ * L_ * L_;

    float* Sptr;
    if ((long long)out_size >= ctx_elems + attn_elems)
        Sptr = out + ((long long)out_size - attn_elems);
    else
        Sptr = out + ctx_elems;

    static int attr_done = 0;
    const int qk_smem = QK_STAGE_U * 3 * 4;
    const int av_smem = AV_STAGE_F * 3 * 4 + 512;
    if (!attr_done) {
        cudaFuncSetAttribute(qk_exp_kernel, cudaFuncAttributeMaxDynamicSharedMemorySize, qk_smem);
        cudaFuncSetAttribute(av_fused_kernel, cudaFuncAttributeMaxDynamicSharedMemorySize, av_smem);
        attr_done = 1;
    }

    float* Eptr;
    cudaGetSymbolAddress((void**)&Eptr, g_E);

    cvt_q_kernel<<<(B_ * 128 * 16 * 32) / 256, 256>>>(Q);
    cvt_k_kernel<<<(B_ * 256 * 16 * 32) / 256, 256>>>(K);
    cvt_v_kernel<<<(B_ * L_ * D_ / 4) / 256, 256>>>(V);

    dim3 g1(L_ / 128, L_ / 128, B_);
    qk_exp_kernel<<<g1, 256, qk_smem>>>(Eptr, if_draw);

    rowinv_kernel<<<(B_ * L_) / 8, 256>>>();

    dim3 g2(D_ / 128, L_ / 128, B_);
    av_fused_kernel<<<g2, 256, av_smem>>>(out, Sptr);
}

// round 10
// speedup vs baseline: 1.1374x; 1.0143x over previous
#include <cuda_runtime.h>
#include <cuda_bf16.h>

#define B_  16
#define L_  2048
#define D_  256

// Scratch (mma-fragment-major layouts; see converters):
__device__ uint4  g_Qfr[(size_t)B_ * 128 * 16 * 32];
__device__ uint2  g_Kfr[(size_t)B_ * 256 * 16 * 32];
__device__ float  g_Vp[(size_t)B_ * L_ * D_];
__device__ float  g_E[(size_t)B_ * L_ * L_];
__device__ float  g_part[(size_t)B_ * L_ * 64];
__device__ float  g_inv[(size_t)B_ * L_];

__device__ __forceinline__ unsigned f2tf32(float x) {
    unsigned u;
    asm("cvt.rna.tf32.f32 %0, %1;" : "=r"(u) : "f"(x));
    return u;
}
__device__ __forceinline__ float f2tf32f(float x) { return __uint_as_float(f2tf32(x)); }

__device__ __forceinline__ unsigned pack_bf16x2(float lo, float hi) {
    unsigned r;
    asm("cvt.rn.bf16x2.f32 %0, %1, %2;" : "=r"(r) : "f"(hi), "f"(lo));
    return r;
}
__device__ __forceinline__ void mma_bf16(float* c, const unsigned* a, const unsigned* b) {
    asm volatile(
        "mma.sync.aligned.m16n8k16.row.col.f32.bf16.bf16.f32 "
        "{%0,%1,%2,%3}, {%4,%5,%6,%7}, {%8,%9}, {%0,%1,%2,%3};"
        : "+f"(c[0]), "+f"(c[1]), "+f"(c[2]), "+f"(c[3])
        : "r"(a[0]), "r"(a[1]), "r"(a[2]), "r"(a[3]), "r"(b[0]), "r"(b[1]));
}
__device__ __forceinline__ void mma_tf32(float* c, const unsigned* a, const unsigned* b) {
    asm volatile(
        "mma.sync.aligned.m16n8k8.row.col.f32.tf32.tf32.f32 "
        "{%0,%1,%2,%3}, {%4,%5,%6,%7}, {%8,%9}, {%0,%1,%2,%3};"
        : "+f"(c[0]), "+f"(c[1]), "+f"(c[2]), "+f"(c[3])
        : "r"(a[0]), "r"(a[1]), "r"(a[2]), "r"(a[3]), "r"(b[0]), "r"(b[1]));
}
__device__ __forceinline__ void cp_async16(unsigned dst, const void* src) {
    asm volatile("cp.async.cg.shared.global [%0], [%1], 16;" :: "r"(dst), "l"(src));
}
#define CP_COMMIT() asm volatile("cp.async.commit_group;" ::: "memory")
#define CP_WAIT1()  asm volatile("cp.async.wait_group 1;" ::: "memory")

// ---------------------------------------------------------------------------
// Converter A: Q -> bf16 fragment quads.
// ---------------------------------------------------------------------------
__global__ void cvt_q_kernel(const float* __restrict__ Q) {
    const int j = blockIdx.x * 256 + threadIdx.x;
    const int lane = j & 31, kc = (j >> 5) & 15, qt = (j >> 9) & 127, b = j >> 16;
    const int g = lane >> 2, qd = lane & 3;
    const float* base = Q + ((size_t)(b * L_) + qt * 16) * D_ + kc * 16 + qd * 2;
    const float2 r0a = *(const float2*)(base + (size_t)g * D_);
    const float2 r0b = *(const float2*)(base + (size_t)g * D_ + 8);
    const float2 r1a = *(const float2*)(base + (size_t)(g + 8) * D_);
    const float2 r1b = *(const float2*)(base + (size_t)(g + 8) * D_ + 8);
    uint4 out;
    out.x = pack_bf16x2(r0a.x, r0a.y);
    out.y = pack_bf16x2(r1a.x, r1a.y);
    out.z = pack_bf16x2(r0b.x, r0b.y);
    out.w = pack_bf16x2(r1b.x, r1b.y);
    g_Qfr[j] = out;
}

// ---------------------------------------------------------------------------
// Converter B: K -> bf16 fragment duos.
// ---------------------------------------------------------------------------
__global__ void cvt_k_kernel(const float* __restrict__ K) {
    const int j = blockIdx.x * 256 + threadIdx.x;
    const int lane = j & 31, kc = (j >> 5) & 15, nt = (j >> 9) & 255, b = j >> 17;
    const int g = lane >> 2, qd = lane & 3;
    const float* base = K + ((size_t)(b * L_) + nt * 8 + g) * D_ + kc * 16 + qd * 2;
    const float2 a = *(const float2*)(base);
    const float2 c = *(const float2*)(base + 8);
    uint2 out;
    out.x = pack_bf16x2(a.x, a.y);
    out.y = pack_bf16x2(c.x, c.y);
    g_Kfr[j] = out;
}

// ---------------------------------------------------------------------------
// Converter C: V -> tf32-rounded permuted layout.
// ---------------------------------------------------------------------------
__global__ void cvt_v_kernel(const float* __restrict__ V) {
    const size_t i = (size_t)blockIdx.x * blockDim.x + threadIdx.x;
    const float4 v = ((const float4*)V)[i];
    const size_t i4 = i * 4;
    const int d   = (int)(i4 & (D_ - 1));
    const int kr  = (int)((i4 >> 8) & (L_ - 1));
    const int bb_ = (int)(i4 >> 19);
    const int ktile = kr >> 5, kk = kr & 31;
    const int ks = kk >> 3, p = (kk >> 2) & 1, qd = kk & 3;
    float* dst = g_Vp + ((size_t)(bb_ * 64 + ktile)) * 8192
                      + (size_t)((ks * 4 + qd) * 256) * 2 + p;
    dst[(d + 0) * 2] = f2tf32f(v.x);
    dst[(d + 1) * 2] = f2tf32f(v.y);
    dst[(d + 2) * 2] = f2tf32f(v.z);
    dst[(d + 3) * 2] = f2tf32f(v.w);
}

// ---------------------------------------------------------------------------
// Kernel 1: E = tf32(exp(scale * Q K^T)) quads + partial row sums.
// ---------------------------------------------------------------------------
#define QK_STAGE_U 4096

__global__ __launch_bounds__(256, 2)
void qk_exp_kernel(float* __restrict__ E_out,
                   const int* __restrict__ if_draw) {
    extern __shared__ unsigned smem_u[];
    const unsigned sbase = (unsigned)__cvta_generic_to_shared(smem_u);

    const int b  = blockIdx.z;
    const int by = blockIdx.y;
    const int kx = blockIdx.x;
    const int q0 = by * 128;
    const int k0 = kx * 128;

    const int tid  = threadIdx.x;
    const int lane = tid & 31;
    const int wid  = tid >> 5;
    const int wmid = wid & 1;
    const int wnid = wid >> 1;
    const int g    = lane >> 2;
    const int qd   = lane & 3;

    float acc[4][4][4] = {};

    auto load_stage = [&](int ss, int kt16) {
        const unsigned qdst = sbase + (unsigned)ss * QK_STAGE_U * 4;
        const unsigned kdst = qdst + 2048 * 4;
        #pragma unroll
        for (int t = 0; t < 2; t++) {
            const int idx = tid + t * 256;
            {
                const int qtl = idx >> 6, rem = idx & 63;
                const uint4* src = g_Qfr + ((size_t)(b * 128 + (q0 >> 4) + qtl) * 512
                                            + kt16 * 32 + rem);
                cp_async16(qdst + (unsigned)idx * 16, src);
            }
            {
                const int ntl = idx >> 5, rem = idx & 31;
                const uint2* src = g_Kfr + ((size_t)(b * 256 + (k0 >> 3) + ntl) * 512
                                            + kt16 * 32 + rem * 2);
                cp_async16(kdst + (unsigned)idx * 16, src);
            }
        }
    };

    load_stage(0, 0); CP_COMMIT();
    load_stage(1, 2); CP_COMMIT();

    for (int i = 0; i < 8; i++) {
        CP_WAIT1();
        __syncthreads();
        if (i + 2 < 8) load_stage((i + 2) % 3, (i + 2) * 2);
        CP_COMMIT();

        const unsigned* Qst = smem_u + (i % 3) * QK_STAGE_U;
        const unsigned* Kst = Qst + 2048;

        #pragma unroll
        for (int ks = 0; ks < 2; ks++) {
            unsigned a[4][4], bb[4][2];
            #pragma unroll
            for (int mt = 0; mt < 4; mt++) {
                const uint4 q4 = *(const uint4*)(Qst + ((wmid * 4 + mt) * 2 + ks) * 128 + lane * 4);
                a[mt][0] = q4.x; a[mt][1] = q4.y; a[mt][2] = q4.z; a[mt][3] = q4.w;
            }
            #pragma unroll
            for (int nt = 0; nt < 4; nt++) {
                const uint2 k2 = *(const uint2*)(Kst + ((wnid * 4 + nt) * 2 + ks) * 64 + lane * 2);
                bb[nt][0] = k2.x; bb[nt][1] = k2.y;
            }
            #pragma unroll
            for (int mt = 0; mt < 4; mt++)
                #pragma unroll
                for (int nt = 0; nt < 4; nt++)
                    mma_bf16(acc[mt][nt], a[mt], bb[nt]);
        }
    }

    const float scale = (if_draw[0] != 0) ? (1.0f / 320.0f) : (1.0f / 16.0f);
    float* Eq = E_out + ((size_t)(b * 16 + by) * 64 + (size_t)kx * 4 + wnid) * 4096;
    const int qdp  = (2 * qd) & 3;
    const int hoff = (qd >> 1) * 2;

    #pragma unroll
    for (int mt = 0; mt < 4; mt++) {
        float slo = 0.f, shi = 0.f;
        const int r16 = wmid * 4 + mt;
        #pragma unroll
        for (int nt = 0; nt < 4; nt++) {
            float e0 = f2tf32f(__expf(scale * acc[mt][nt][0]));
            float e1 = f2tf32f(__expf(scale * acc[mt][nt][1]));
            float e2 = f2tf32f(__expf(scale * acc[mt][nt][2]));
            float e3 = f2tf32f(__expf(scale * acc[mt][nt][3]));
            slo += e0 + e1;
            shi += e2 + e3;
            const int off = r16 * 512 + nt * 128 + (g * 4 + qdp) * 4 + hoff;
            float2 p0 = {e0, e2};
            float2 p1 = {e1, e3};
            *(float2*)(Eq + off)     = p0;
            *(float2*)(Eq + off + 4) = p1;
        }
        slo += __shfl_xor_sync(0xffffffffu, slo, 1);
        slo += __shfl_xor_sync(0xffffffffu, slo, 2);
        shi += __shfl_xor_sync(0xffffffffu, shi, 1);
        shi += __shfl_xor_sync(0xffffffffu, shi, 2);
        if (qd == 0) {
            const size_t rbase = (size_t)(b * L_ + q0 + wmid * 64 + mt * 16 + g) * 64 + kx * 4 + wnid;
            g_part[rbase]          = slo;
            g_part[rbase + 8 * 64] = shi;
        }
    }
}

// ---------------------------------------------------------------------------
// Kernel 1b: reduce 64 partials per row -> g_inv = 1/rowsum.
// ---------------------------------------------------------------------------
__global__ void rowinv_kernel() {
    const int row  = blockIdx.x * 8 + (threadIdx.x >> 5);
    const int lane = threadIdx.x & 31;
    const float* p = g_part + (size_t)row * 64;
    float s = p[lane] + p[lane + 32];
    #pragma unroll
    for (int o = 16; o > 0; o >>= 1)
        s += __shfl_xor_sync(0xffffffffu, s, o);
    if (lane == 0) g_inv[row] = 1.0f / s;
}

// ---------------------------------------------------------------------------
// Kernel 2: O = (E @ V) * inv ; attn = E * inv.
// One CTA per 128-row q-panel covering FULL D=256 (E read once from DRAM).
// 512 threads = 16 warps (2 m-halves x 8 n-groups), warp tile 64x32.
// ---------------------------------------------------------------------------
#define AV_A_F     4096
#define AV_V_F     8320     // 16 rows x (512 + 8 pad)
#define AV_STAGE_F (AV_A_F + AV_V_F)

__global__ __launch_bounds__(512, 1)
void av_fused_kernel(float* __restrict__ O,
                     float* __restrict__ attn) {
    extern __shared__ float smem_f[];
    const unsigned sbase = (unsigned)__cvta_generic_to_shared(smem_f);
    float* inv_s = smem_f + 3 * AV_STAGE_F;

    const int b  = blockIdx.z;
    const int q0 = blockIdx.y * 128;

    const float* Ab = g_E  + ((size_t)(b * 16 + blockIdx.y) * 64) * 4096;
    const float* Vb = g_Vp + (size_t)b * 64 * 8192;

    const int tid  = threadIdx.x;
    const int lane = tid & 31;
    const int wid  = tid >> 5;            // 0..15
    const int wm16 = (wid & 1) * 4;       // m half
    const int wn   = (wid >> 1) * 32;     // n group (0..224)
    const int g    = lane >> 2;
    const int qd   = lane & 3;

    // attn-write decode (per-lane constants)
    const int ntk = lane >> 3;
    const int m   = lane & 7;
    const int cw  = (m >> 1) + (m & 1) * 4;

    float acc[4][4][4] = {};

    if (tid < 128) inv_s[tid] = g_inv[b * L_ + q0 + tid];

    auto load_stage = [&](int ss, int ktile) {
        const unsigned adst = sbase + (unsigned)ss * AV_STAGE_F * 4;
        const unsigned vdst = adst + AV_A_F * 4;
        const float* Agm = Ab + (size_t)ktile * 4096;
        const float* Vgm = Vb + (size_t)ktile * 8192;
        #pragma unroll
        for (int t = 0; t < 2; t++) {               // A: 1024 quads
            const int idx = tid + t * 512;
            cp_async16(adst + (unsigned)idx * 16, Agm + idx * 4);
        }
        #pragma unroll
        for (int t = 0; t < 4; t++) {               // V: 2048 quads
            const int idx = tid + t * 512;
            const int vrow = idx >> 7, vrem = (idx & 127) * 4;
            cp_async16(vdst + (unsigned)(vrow * 520 + vrem) * 4, Vgm + vrow * 512 + vrem);
        }
    };

    load_stage(0, 0); CP_COMMIT();
    load_stage(1, 1); CP_COMMIT();

    float* attn_b = attn + (size_t)b * L_ * L_;

    for (int i = 0; i < 64; i++) {
        CP_WAIT1();
        __syncthreads();
        if (i + 2 < 64) load_stage((i + 2) % 3, i + 2);
        CP_COMMIT();

        const float* Ast = smem_f + (i % 3) * AV_STAGE_F;
        const float* Vst = Ast + AV_A_F;

        // attn = E * inv — coalesced row stores (each CTA owns its panel).
        #pragma unroll
        for (int t = 0; t < 4; t++) {
            const int grp = wid * 4 + t;       // 0..63 = (r16, gg)
            const int r16 = grp >> 3, gg = grp & 7;
            const float2 e = *(const float2*)(Ast + r16 * 512 + ntk * 128 + gg * 16 + m * 2);
            const int lr0 = r16 * 16 + gg;
            const int col = i * 32 + ntk * 8 + cw;
            attn_b[(size_t)(q0 + lr0) * L_ + col]     = e.x * inv_s[lr0];
            attn_b[(size_t)(q0 + lr0 + 8) * L_ + col] = e.y * inv_s[lr0 + 8];
        }

        #pragma unroll
        for (int ks = 0; ks < 4; ks++) {
            unsigned a[4][4], bb[4][2];
            #pragma unroll
            for (int mt = 0; mt < 4; mt++) {
                const uint4 q4 = *(const uint4*)(Ast + (wm16 + mt) * 512 + ks * 128 + lane * 4);
                a[mt][0] = q4.x; a[mt][1] = q4.y; a[mt][2] = q4.z; a[mt][3] = q4.w;
            }
            #pragma unroll
            for (int nt = 0; nt < 4; nt++) {
                const int nc = wn + nt * 8 + g;
                const float2 v01 = *(const float2*)(Vst + (ks * 4 + qd) * 520 + nc * 2);
                bb[nt][0] = __float_as_uint(v01.x);
                bb[nt][1] = __float_as_uint(v01.y);
            }
            #pragma unroll
            for (int mt = 0; mt < 4; mt++)
                #pragma unroll
                for (int nt = 0; nt < 4; nt++)
                    mma_tf32(acc[mt][nt], a[mt], bb[nt]);
        }
    }

    float* Ob = O + (size_t)b * L_ * D_;
    #pragma unroll
    for (int mt = 0; mt < 4; mt++) {
        const int lrow = (wid & 1) * 64 + mt * 16 + g;
        const int row  = q0 + lrow;
        const float iv0 = inv_s[lrow];
        const float iv1 = inv_s[lrow + 8];
        #pragma unroll
        for (int nt = 0; nt < 4; nt++) {
            const int col = wn + nt * 8 + 2 * qd;
            float2 v0 = {acc[mt][nt][0] * iv0, acc[mt][nt][1] * iv0};
            float2 v1 = {acc[mt][nt][2] * iv1, acc[mt][nt][3] * iv1};
            *(float2*)(Ob + (size_t)row * D_ + col)       = v0;
            *(float2*)(Ob + (size_t)(row + 8) * D_ + col) = v1;
        }
    }
}

// ---------------------------------------------------------------------------
// Launch
// ---------------------------------------------------------------------------
extern "C" void kernel_launch(void* const* d_in, const int* in_sizes, int n_in,
                              void* d_out, int out_size) {
    const float* Q = (const float*)d_in[0];
    const float* K = (const float*)d_in[1];
    const float* V = (const float*)d_in[2];
    const int* if_draw = (const int*)d_in[4];

    float* out = (float*)d_out;

    const long long ctx_elems  = (long long)B_ * L_ * D_;
    const long long attn_elems = (long long)B_ * L_ * L_;

    float* Sptr;
    if ((long long)out_size >= ctx_elems + attn_elems)
        Sptr = out + ((long long)out_size - attn_elems);
    else
        Sptr = out + ctx_elems;

    static int attr_done = 0;
    const int qk_smem = QK_STAGE_U * 3 * 4;          // 49152 B
    const int av_smem = AV_STAGE_F * 3 * 4 + 512;    // 149504 B
    if (!attr_done) {
        cudaFuncSetAttribute(qk_exp_kernel, cudaFuncAttributeMaxDynamicSharedMemorySize, qk_smem);
        cudaFuncSetAttribute(av_fused_kernel, cudaFuncAttributeMaxDynamicSharedMemorySize, av_smem);
        attr_done = 1;
    }

    float* Eptr;
    cudaGetSymbolAddress((void**)&Eptr, g_E);

    cvt_q_kernel<<<(B_ * 128 * 16 * 32) / 256, 256>>>(Q);
    cvt_k_kernel<<<(B_ * 256 * 16 * 32) / 256, 256>>>(K);
    cvt_v_kernel<<<(B_ * L_ * D_ / 4) / 256, 256>>>(V);

    dim3 g1(L_ / 128, L_ / 128, B_);
    qk_exp_kernel<<<g1, 256, qk_smem>>>(Eptr, if_draw);

    rowinv_kernel<<<(B_ * L_) / 8, 256>>>();

    dim3 g2(1, L_ / 128, B_);
    av_fused_kernel<<<g2, 512, av_smem>>>(out, Sptr);
}

// round 12
// speedup vs baseline: 1.7626x; 1.5496x over previous
#include <cuda_runtime.h>
#include <cuda_bf16.h>
#include <cuda_fp16.h>

#define B_  16
#define L_  2048
#define D_  256

// Scratch:
//  g_Qfr : Q bf16 quads [b][qtile128][kchunk16][lane32] (uint4)  -- qk A frags
//  g_Kfr : K bf16 duos  [b][ntile256][kchunk16][lane32] (uint2)  -- qk B frags
//  g_Vf  : V fp16 duos  [b][kchunk128][ntile32][lane32] (uint2)  -- av B frags
//  g_Ef  : E fp16 quads [b*16+qp][r16 8][kchunk128][lane32] (uint4) -- av A frags
__device__ uint4  g_Qfr[(size_t)B_ * 128 * 16 * 32];
__device__ uint2  g_Kfr[(size_t)B_ * 256 * 16 * 32];
__device__ uint2  g_Vf[(size_t)B_ * 128 * 32 * 32];
__device__ uint4  g_Ef[(size_t)B_ * 16 * 8 * 128 * 32];
__device__ float  g_part[(size_t)B_ * L_ * 64];
__device__ float  g_inv[(size_t)B_ * L_];

__device__ __forceinline__ unsigned pack_bf16x2(float lo, float hi) {
    unsigned r;
    asm("cvt.rn.bf16x2.f32 %0, %1, %2;" : "=r"(r) : "f"(hi), "f"(lo));
    return r;
}
__device__ __forceinline__ unsigned pack_f16x2(float lo, float hi) {
    unsigned r;
    asm("cvt.rn.f16x2.f32 %0, %1, %2;" : "=r"(r) : "f"(hi), "f"(lo));
    return r;
}
__device__ __forceinline__ void mma_bf16(float* c, const unsigned* a, const unsigned* b) {
    asm volatile(
        "mma.sync.aligned.m16n8k16.row.col.f32.bf16.bf16.f32 "
        "{%0,%1,%2,%3}, {%4,%5,%6,%7}, {%8,%9}, {%0,%1,%2,%3};"
        : "+f"(c[0]), "+f"(c[1]), "+f"(c[2]), "+f"(c[3])
        : "r"(a[0]), "r"(a[1]), "r"(a[2]), "r"(a[3]), "r"(b[0]), "r"(b[1]));
}
__device__ __forceinline__ void mma_f16(float* c, const unsigned* a, const unsigned* b) {
    asm volatile(
        "mma.sync.aligned.m16n8k16.row.col.f32.f16.f16.f32 "
        "{%0,%1,%2,%3}, {%4,%5,%6,%7}, {%8,%9}, {%0,%1,%2,%3};"
        : "+f"(c[0]), "+f"(c[1]), "+f"(c[2]), "+f"(c[3])
        : "r"(a[0]), "r"(a[1]), "r"(a[2]), "r"(a[3]), "r"(b[0]), "r"(b[1]));
}
__device__ __forceinline__ void cp_async16(unsigned dst, const void* src) {
    asm volatile("cp.async.cg.shared.global [%0], [%1], 16;" :: "r"(dst), "l"(src));
}
#define CP_COMMIT() asm volatile("cp.async.commit_group;" ::: "memory")
#define CP_WAIT1()  asm volatile("cp.async.wait_group 1;" ::: "memory")
#define CP_WAIT2()  asm volatile("cp.async.wait_group 2;" ::: "memory")

// ---------------------------------------------------------------------------
// Converter A: Q -> bf16 fragment quads (unchanged R10).
// ---------------------------------------------------------------------------
__global__ void cvt_q_kernel(const float* __restrict__ Q) {
    const int j = blockIdx.x * 256 + threadIdx.x;
    const int lane = j & 31, kc = (j >> 5) & 15, qt = (j >> 9) & 127, b = j >> 16;
    const int g = lane >> 2, qd = lane & 3;
    const float* base = Q + ((size_t)(b * L_) + qt * 16) * D_ + kc * 16 + qd * 2;
    const float2 r0a = *(const float2*)(base + (size_t)g * D_);
    const float2 r0b = *(const float2*)(base + (size_t)g * D_ + 8);
    const float2 r1a = *(const float2*)(base + (size_t)(g + 8) * D_);
    const float2 r1b = *(const float2*)(base + (size_t)(g + 8) * D_ + 8);
    uint4 out;
    out.x = pack_bf16x2(r0a.x, r0a.y);
    out.y = pack_bf16x2(r1a.x, r1a.y);
    out.z = pack_bf16x2(r0b.x, r0b.y);
    out.w = pack_bf16x2(r1b.x, r1b.y);
    g_Qfr[j] = out;
}

// ---------------------------------------------------------------------------
// Converter B: K -> bf16 fragment duos (unchanged R10).
// ---------------------------------------------------------------------------
__global__ void cvt_k_kernel(const float* __restrict__ K) {
    const int j = blockIdx.x * 256 + threadIdx.x;
    const int lane = j & 31, kc = (j >> 5) & 15, nt = (j >> 9) & 255, b = j >> 17;
    const int g = lane >> 2, qd = lane & 3;
    const float* base = K + ((size_t)(b * L_) + nt * 8 + g) * D_ + kc * 16 + qd * 2;
    const float2 a = *(const float2*)(base);
    const float2 c = *(const float2*)(base + 8);
    uint2 out;
    out.x = pack_bf16x2(a.x, a.y);
    out.y = pack_bf16x2(c.x, c.y);
    g_Kfr[j] = out;
}

// ---------------------------------------------------------------------------
// Converter C: V -> fp16 B-fragment duos.
// duo(b,kc,nt,lane(g,qd)) = { f16x2(V[kc16+2qd][nt8+g], V[kc16+2qd+1][..]),
//                             f16x2(V[kc16+2qd+8][..], V[kc16+2qd+9][..]) }
// ---------------------------------------------------------------------------
__global__ void cvt_v_f16(const float* __restrict__ V) {
    const int j = blockIdx.x * 256 + threadIdx.x;   // 2,097,152 duos
    const int lane = j & 31, nt = (j >> 5) & 31, kc = (j >> 10) & 127, b = j >> 17;
    const int g = lane >> 2, qd = lane & 3;
    const float* Vb = V + (size_t)b * L_ * D_;
    const int col = nt * 8 + g;
    const int r0  = kc * 16 + 2 * qd;
    const float v00 = Vb[(size_t)r0 * D_ + col];
    const float v01 = Vb[(size_t)(r0 + 1) * D_ + col];
    const float v10 = Vb[(size_t)(r0 + 8) * D_ + col];
    const float v11 = Vb[(size_t)(r0 + 9) * D_ + col];
    uint2 out;
    out.x = pack_f16x2(v00, v01);
    out.y = pack_f16x2(v10, v11);
    g_Vf[j] = out;
}

// ---------------------------------------------------------------------------
// Kernel 1: E = fp16(exp(scale * Q K^T)) quads + partial row sums.
// Mainloop identical to R10; epilogue packs fp16 quads (no shuffles).
// ---------------------------------------------------------------------------
#define QK_STAGE_U 4096

__global__ __launch_bounds__(256, 2)
void qk_exp_kernel(const int* __restrict__ if_draw) {
    extern __shared__ unsigned smem_u[];
    const unsigned sbase = (unsigned)__cvta_generic_to_shared(smem_u);

    const int b  = blockIdx.z;
    const int by = blockIdx.y;
    const int kx = blockIdx.x;
    const int q0 = by * 128;
    const int k0 = kx * 128;

    const int tid  = threadIdx.x;
    const int lane = tid & 31;
    const int wid  = tid >> 5;
    const int wmid = wid & 1;
    const int wnid = wid >> 1;
    const int g    = lane >> 2;
    const int qd   = lane & 3;

    float acc[4][4][4] = {};

    auto load_stage = [&](int ss, int kt16) {
        const unsigned qdst = sbase + (unsigned)ss * QK_STAGE_U * 4;
        const unsigned kdst = qdst + 2048 * 4;
        #pragma unroll
        for (int t = 0; t < 2; t++) {
            const int idx = tid + t * 256;
            {
                const int qtl = idx >> 6, rem = idx & 63;
                const uint4* src = g_Qfr + ((size_t)(b * 128 + (q0 >> 4) + qtl) * 512
                                            + kt16 * 32 + rem);
                cp_async16(qdst + (unsigned)idx * 16, src);
            }
            {
                const int ntl = idx >> 5, rem = idx & 31;
                const uint2* src = g_Kfr + ((size_t)(b * 256 + (k0 >> 3) + ntl) * 512
                                            + kt16 * 32 + rem * 2);
                cp_async16(kdst + (unsigned)idx * 16, src);
            }
        }
    };

    load_stage(0, 0); CP_COMMIT();
    load_stage(1, 2); CP_COMMIT();

    for (int i = 0; i < 8; i++) {
        CP_WAIT1();
        __syncthreads();
        if (i + 2 < 8) load_stage((i + 2) % 3, (i + 2) * 2);
        CP_COMMIT();

        const unsigned* Qst = smem_u + (i % 3) * QK_STAGE_U;
        const unsigned* Kst = Qst + 2048;

        #pragma unroll
        for (int ks = 0; ks < 2; ks++) {
            unsigned a[4][4], bb[4][2];
            #pragma unroll
            for (int mt = 0; mt < 4; mt++) {
                const uint4 q4 = *(const uint4*)(Qst + ((wmid * 4 + mt) * 2 + ks) * 128 + lane * 4);
                a[mt][0] = q4.x; a[mt][1] = q4.y; a[mt][2] = q4.z; a[mt][3] = q4.w;
            }
            #pragma unroll
            for (int nt = 0; nt < 4; nt++) {
                const uint2 k2 = *(const uint2*)(Kst + ((wnid * 4 + nt) * 2 + ks) * 64 + lane * 2);
                bb[nt][0] = k2.x; bb[nt][1] = k2.y;
            }
            #pragma unroll
            for (int mt = 0; mt < 4; mt++)
                #pragma unroll
                for (int nt = 0; nt < 4; nt++)
                    mma_bf16(acc[mt][nt], a[mt], bb[nt]);
        }
    }

    // Epilogue: exp -> fp16 quads; partial row sums.
    const float scale = (if_draw[0] != 0) ? (1.0f / 320.0f) : (1.0f / 16.0f);
    uint4* Eq = g_Ef + (size_t)(b * 16 + by) * 32768;

    #pragma unroll
    for (int mt = 0; mt < 4; mt++) {
        float slo = 0.f, shi = 0.f;
        const int r16 = wmid * 4 + mt;
        #pragma unroll
        for (int c = 0; c < 2; c++) {
            const int nt0 = 2 * c, nt1 = 2 * c + 1;
            float e00 = __expf(scale * acc[mt][nt0][0]);
            float e01 = __expf(scale * acc[mt][nt0][1]);
            float e02 = __expf(scale * acc[mt][nt0][2]);
            float e03 = __expf(scale * acc[mt][nt0][3]);
            float e10 = __expf(scale * acc[mt][nt1][0]);
            float e11 = __expf(scale * acc[mt][nt1][1]);
            float e12 = __expf(scale * acc[mt][nt1][2]);
            float e13 = __expf(scale * acc[mt][nt1][3]);
            slo += e00 + e01 + e10 + e11;
            shi += e02 + e03 + e12 + e13;
            uint4 q;
            q.x = pack_f16x2(e00, e01);
            q.y = pack_f16x2(e02, e03);
            q.z = pack_f16x2(e10, e11);
            q.w = pack_f16x2(e12, e13);
            const int kchunk = kx * 8 + wnid * 2 + c;
            Eq[(size_t)(r16 * 128 + kchunk) * 32 + lane] = q;
        }
        slo += __shfl_xor_sync(0xffffffffu, slo, 1);
        slo += __shfl_xor_sync(0xffffffffu, slo, 2);
        shi += __shfl_xor_sync(0xffffffffu, shi, 1);
        shi += __shfl_xor_sync(0xffffffffu, shi, 2);
        if (qd == 0) {
            const size_t rbase = (size_t)(b * L_ + q0 + wmid * 64 + mt * 16 + g) * 64 + kx * 4 + wnid;
            g_part[rbase]          = slo;
            g_part[rbase + 8 * 64] = shi;
        }
    }
}

// ---------------------------------------------------------------------------
// Kernel 1b: reduce 64 partials per row -> g_inv = 1/rowsum.
// ---------------------------------------------------------------------------
__global__ void rowinv_kernel() {
    const int row  = blockIdx.x * 8 + (threadIdx.x >> 5);
    const int lane = threadIdx.x & 31;
    const float* p = g_part + (size_t)row * 64;
    float s = p[lane] + p[lane + 32];
    #pragma unroll
    for (int o = 16; o > 0; o >>= 1)
        s += __shfl_xor_sync(0xffffffffu, s, o);
    if (lane == 0) g_inv[row] = 1.0f / s;
}

// ---------------------------------------------------------------------------
// Kernel 2 (fp16 mma): O = (E @ V) * inv ; attn = fp32(E) * inv.
// One CTA per q-panel (full D=256), 512 threads, 4-stage cp.async pipeline.
// Stage: A 512 quads (8KB) + V 1024 16B-chunks (16KB) = 24576 B.
// ---------------------------------------------------------------------------
#define AV_STAGE_B 24576

__global__ __launch_bounds__(512, 1)
void av_f16_kernel(float* __restrict__ O,
                   float* __restrict__ attn) {
    extern __shared__ unsigned char smem_raw[];
    const unsigned sbase = (unsigned)__cvta_generic_to_shared(smem_raw);
    float* inv_s = (float*)(smem_raw + 4 * AV_STAGE_B);

    const int b  = blockIdx.y;
    const int qp = blockIdx.x;
    const int q0 = qp * 128;

    const uint4* Ab = g_Ef + (size_t)(b * 16 + qp) * 32768;
    const unsigned char* Vb = (const unsigned char*)(g_Vf + (size_t)b * 131072);

    const int tid  = threadIdx.x;
    const int lane = tid & 31;
    const int wid  = tid >> 5;
    const int wm16 = (wid & 1) * 4;       // r16 base
    const int ntb  = (wid >> 1) * 4;      // ntile base (0..28)
    const int g    = lane >> 2;
    const int qd   = lane & 3;

    // attn-write decode from this thread's staged quad (slot = tid)
    const int aw_r16 = tid >> 6;
    const int aw_kcl = (tid >> 5) & 1;
    const int aw_g   = (tid & 31) >> 2;
    const int aw_qd  = tid & 3;

    float acc[4][4][4] = {};

    if (tid < 128) inv_s[tid] = g_inv[b * L_ + q0 + tid];

    auto load_stage = [&](int ss, int i) {
        const unsigned adst = sbase + (unsigned)ss * AV_STAGE_B;
        const unsigned vdst = adst + 8192;
        {   // A: 512 quads, 1 per thread
            const int r16 = tid >> 6, kcl = (tid >> 5) & 1, ln = tid & 31;
            cp_async16(adst + (unsigned)tid * 16,
                       Ab + (size_t)r16 * 4096 + (2 * i + kcl) * 32 + ln);
        }
        #pragma unroll
        for (int t = 0; t < 2; t++) {   // V: 1024 chunks
            const int idx = tid + t * 512;
            cp_async16(vdst + (unsigned)idx * 16, Vb + (size_t)i * 16384 + idx * 16);
        }
    };

    load_stage(0, 0); CP_COMMIT();
    load_stage(1, 1); CP_COMMIT();
    load_stage(2, 2); CP_COMMIT();

    float* attn_b = attn + (size_t)b * L_ * L_;

    for (int i = 0; i < 64; i++) {
        CP_WAIT2();
        __syncthreads();
        if (i + 3 < 64) load_stage((i + 3) & 3, i + 3);
        CP_COMMIT();

        const unsigned char* Ast = smem_raw + (i & 3) * AV_STAGE_B;
        const unsigned char* Vst = Ast + 8192;

        // attn = fp32(E) * inv : one quad per thread, contiguous float2 stores.
        {
            const uint4 q4 = *(const uint4*)(Ast + tid * 16);
            const int lr0 = aw_r16 * 16 + aw_g, lr1 = lr0 + 8;
            const float iv0 = inv_s[lr0], iv1 = inv_s[lr1];
            const int colb = i * 32 + aw_kcl * 16 + 2 * aw_qd;
            float2 p;
            float2 a0 = __half22float2(*(const __half2*)&q4.x);
            p.x = a0.x * iv0; p.y = a0.y * iv0;
            *(float2*)(attn_b + (size_t)(q0 + lr0) * L_ + colb) = p;
            float2 a1 = __half22float2(*(const __half2*)&q4.z);
            p.x = a1.x * iv0; p.y = a1.y * iv0;
            *(float2*)(attn_b + (size_t)(q0 + lr0) * L_ + colb + 8) = p;
            float2 a2 = __half22float2(*(const __half2*)&q4.y);
            p.x = a2.x * iv1; p.y = a2.y * iv1;
            *(float2*)(attn_b + (size_t)(q0 + lr1) * L_ + colb) = p;
            float2 a3 = __half22float2(*(const __half2*)&q4.w);
            p.x = a3.x * iv1; p.y = a3.y * iv1;
            *(float2*)(attn_b + (size_t)(q0 + lr1) * L_ + colb + 8) = p;
        }

        #pragma unroll
        for (int kc = 0; kc < 2; kc++) {
            unsigned a[4][4], bb[4][2];
            #pragma unroll
            for (int mt = 0; mt < 4; mt++) {
                const uint4 q4 = *(const uint4*)(Ast + (((wm16 + mt) * 2 + kc) * 32 + lane) * 16);
                a[mt][0] = q4.x; a[mt][1] = q4.y; a[mt][2] = q4.z; a[mt][3] = q4.w;
            }
            #pragma unroll
            for (int nt = 0; nt < 4; nt++) {
                const uint2 v2 = *(const uint2*)(Vst + (((kc * 32) + ntb + nt) * 32 + lane) * 8);
                bb[nt][0] = v2.x; bb[nt][1] = v2.y;
            }
            #pragma unroll
            for (int mt = 0; mt < 4; mt++)
                #pragma unroll
                for (int nt = 0; nt < 4; nt++)
                    mma_f16(acc[mt][nt], a[mt], bb[nt]);
        }
    }

    float* Ob = O + (size_t)b * L_ * D_;
    #pragma unroll
    for (int mt = 0; mt < 4; mt++) {
        const int lrow = (wid & 1) * 64 + mt * 16 + g;
        const int row  = q0 + lrow;
        const float iv0 = inv_s[lrow];
        const float iv1 = inv_s[lrow + 8];
        #pragma unroll
        for (int nt = 0; nt < 4; nt++) {
            const int col = (ntb + nt) * 8 + 2 * qd;
            float2 v0 = {acc[mt][nt][0] * iv0, acc[mt][nt][1] * iv0};
            float2 v1 = {acc[mt][nt][2] * iv1, acc[mt][nt][3] * iv1};
            *(float2*)(Ob + (size_t)row * D_ + col)       = v0;
            *(float2*)(Ob + (size_t)(row + 8) * D_ + col) = v1;
        }
    }
}

// ---------------------------------------------------------------------------
// Launch
// ---------------------------------------------------------------------------
extern "C" void kernel_launch(void* const* d_in, const int* in_sizes, int n_in,
                              void* d_out, int out_size) {
    const float* Q = (const float*)d_in[0];
    const float* K = (const float*)d_in[1];
    const float* V = (const float*)d_in[2];
    const int* if_draw = (const int*)d_in[4];

    float* out = (float*)d_out;

    const long long ctx_elems  = (long long)B_ * L_ * D_;
    const long long attn_elems = (long long)B_ * L_ * L_;

    float* Sptr;
    if ((long long)out_size >= ctx_elems + attn_elems)
        Sptr = out + ((long long)out_size - attn_elems);
    else
        Sptr = out + ctx_elems;

    static int attr_done = 0;
    const int qk_smem = QK_STAGE_U * 3 * 4;          // 49152 B
    const int av_smem = AV_STAGE_B * 4 + 512;        // 98816 B
    if (!attr_done) {
        cudaFuncSetAttribute(qk_exp_kernel, cudaFuncAttributeMaxDynamicSharedMemorySize, qk_smem);
        cudaFuncSetAttribute(av_f16_kernel, cudaFuncAttributeMaxDynamicSharedMemorySize, av_smem);
        attr_done = 1;
    }

    cvt_q_kernel<<<(B_ * 128 * 16 * 32) / 256, 256>>>(Q);
    cvt_k_kernel<<<(B_ * 256 * 16 * 32) / 256, 256>>>(K);
    cvt_v_f16<<<(B_ * 128 * 32 * 32) / 256, 256>>>(V);

    dim3 g1(L_ / 128, L_ / 128, B_);
    qk_exp_kernel<<<g1, 256, qk_smem>>>(if_draw);

    rowinv_kernel<<<(B_ * L_) / 8, 256>>>();

    dim3 g2(16, B_);                    // (qpanel, b)
    av_f16_kernel<<<g2, 512, av_smem>>>(out, Sptr);
}

// round 13
// speedup vs baseline: 1.7888x; 1.0149x over previous
#include <cuda_runtime.h>
#include <cuda_bf16.h>
#include <cuda_fp16.h>

#define B_  16
#define L_  2048
#define D_  256

// Scratch:
//  g_Qfr : Q bf16 quads [b][qtile128][kchunk16][lane32] (uint4)  -- qk A frags
//  g_Kfr : K bf16 duos  [b][ntile256][kchunk16][lane32] (uint2)  -- qk B frags
//  g_Vf  : V fp16 duos  [b][kchunk128][ntile32][lane32] (uint2)  -- av B frags
//  g_Ef  : E fp16 quads [b*16+qp][r16 8][kchunk128][lane32] (uint4) -- av A frags
__device__ uint4  g_Qfr[(size_t)B_ * 128 * 16 * 32];
__device__ uint2  g_Kfr[(size_t)B_ * 256 * 16 * 32];
__device__ uint2  g_Vf[(size_t)B_ * 128 * 32 * 32];
__device__ uint4  g_Ef[(size_t)B_ * 16 * 8 * 128 * 32];
__device__ float  g_part[(size_t)B_ * L_ * 64];

__device__ __forceinline__ unsigned pack_bf16x2(float lo, float hi) {
    unsigned r;
    asm("cvt.rn.bf16x2.f32 %0, %1, %2;" : "=r"(r) : "f"(hi), "f"(lo));
    return r;
}
__device__ __forceinline__ unsigned pack_f16x2(float lo, float hi) {
    unsigned r;
    asm("cvt.rn.f16x2.f32 %0, %1, %2;" : "=r"(r) : "f"(hi), "f"(lo));
    return r;
}
__device__ __forceinline__ void mma_bf16(float* c, const unsigned* a, const unsigned* b) {
    asm volatile(
        "mma.sync.aligned.m16n8k16.row.col.f32.bf16.bf16.f32 "
        "{%0,%1,%2,%3}, {%4,%5,%6,%7}, {%8,%9}, {%0,%1,%2,%3};"
        : "+f"(c[0]), "+f"(c[1]), "+f"(c[2]), "+f"(c[3])
        : "r"(a[0]), "r"(a[1]), "r"(a[2]), "r"(a[3]), "r"(b[0]), "r"(b[1]));
}
__device__ __forceinline__ void mma_f16(float* c, const unsigned* a, const unsigned* b) {
    asm volatile(
        "mma.sync.aligned.m16n8k16.row.col.f32.f16.f16.f32 "
        "{%0,%1,%2,%3}, {%4,%5,%6,%7}, {%8,%9}, {%0,%1,%2,%3};"
        : "+f"(c[0]), "+f"(c[1]), "+f"(c[2]), "+f"(c[3])
        : "r"(a[0]), "r"(a[1]), "r"(a[2]), "r"(a[3]), "r"(b[0]), "r"(b[1]));
}
__device__ __forceinline__ void cp_async16(unsigned dst, const void* src) {
    asm volatile("cp.async.cg.shared.global [%0], [%1], 16;" :: "r"(dst), "l"(src));
}
#define CP_COMMIT() asm volatile("cp.async.commit_group;" ::: "memory")
#define CP_WAIT2()  asm volatile("cp.async.wait_group 2;" ::: "memory")
#define CP_WAIT4()  asm volatile("cp.async.wait_group 4;" ::: "memory")

// ---------------------------------------------------------------------------
// Converter A: Q -> bf16 fragment quads.
// ---------------------------------------------------------------------------
__global__ void cvt_q_kernel(const float* __restrict__ Q) {
    const int j = blockIdx.x * 256 + threadIdx.x;
    const int lane = j & 31, kc = (j >> 5) & 15, qt = (j >> 9) & 127, b = j >> 16;
    const int g = lane >> 2, qd = lane & 3;
    const float* base = Q + ((size_t)(b * L_) + qt * 16) * D_ + kc * 16 + qd * 2;
    const float2 r0a = *(const float2*)(base + (size_t)g * D_);
    const float2 r0b = *(const float2*)(base + (size_t)g * D_ + 8);
    const float2 r1a = *(const float2*)(base + (size_t)(g + 8) * D_);
    const float2 r1b = *(const float2*)(base + (size_t)(g + 8) * D_ + 8);
    uint4 out;
    out.x = pack_bf16x2(r0a.x, r0a.y);
    out.y = pack_bf16x2(r1a.x, r1a.y);
    out.z = pack_bf16x2(r0b.x, r0b.y);
    out.w = pack_bf16x2(r1b.x, r1b.y);
    g_Qfr[j] = out;
}

// ---------------------------------------------------------------------------
// Converter B: K -> bf16 fragment duos.
// ---------------------------------------------------------------------------
__global__ void cvt_k_kernel(const float* __restrict__ K) {
    const int j = blockIdx.x * 256 + threadIdx.x;
    const int lane = j & 31, kc = (j >> 5) & 15, nt = (j >> 9) & 255, b = j >> 17;
    const int g = lane >> 2, qd = lane & 3;
    const float* base = K + ((size_t)(b * L_) + nt * 8 + g) * D_ + kc * 16 + qd * 2;
    const float2 a = *(const float2*)(base);
    const float2 c = *(const float2*)(base + 8);
    uint2 out;
    out.x = pack_bf16x2(a.x, a.y);
    out.y = pack_bf16x2(c.x, c.y);
    g_Kfr[j] = out;
}

// ---------------------------------------------------------------------------
// Converter C: V -> fp16 B-fragment duos.
// ---------------------------------------------------------------------------
__global__ void cvt_v_f16(const float* __restrict__ V) {
    const int j = blockIdx.x * 256 + threadIdx.x;
    const int lane = j & 31, nt = (j >> 5) & 31, kc = (j >> 10) & 127, b = j >> 17;
    const int g = lane >> 2, qd = lane & 3;
    const float* Vb = V + (size_t)b * L_ * D_;
    const int col = nt * 8 + g;
    const int r0  = kc * 16 + 2 * qd;
    const float v00 = Vb[(size_t)r0 * D_ + col];
    const float v01 = Vb[(size_t)(r0 + 1) * D_ + col];
    const float v10 = Vb[(size_t)(r0 + 8) * D_ + col];
    const float v11 = Vb[(size_t)(r0 + 9) * D_ + col];
    uint2 out;
    out.x = pack_f16x2(v00, v01);
    out.y = pack_f16x2(v10, v11);
    g_Vf[j] = out;
}

// ---------------------------------------------------------------------------
// Kernel 1: E = fp16(exp(scale * Q K^T)) quads + partial row sums.
// 4-stage cp.async pipeline (3 in flight).
// ---------------------------------------------------------------------------
#define QK_STAGE_U 4096

__global__ __launch_bounds__(256, 2)
void qk_exp_kernel(const int* __restrict__ if_draw) {
    extern __shared__ unsigned smem_u[];
    const unsigned sbase = (unsigned)__cvta_generic_to_shared(smem_u);

    const int b  = blockIdx.z;
    const int by = blockIdx.y;
    const int kx = blockIdx.x;
    const int q0 = by * 128;
    const int k0 = kx * 128;

    const int tid  = threadIdx.x;
    const int lane = tid & 31;
    const int wid  = tid >> 5;
    const int wmid = wid & 1;
    const int wnid = wid >> 1;
    const int g    = lane >> 2;
    const int qd   = lane & 3;

    float acc[4][4][4] = {};

    auto load_stage = [&](int ss, int kt16) {
        const unsigned qdst = sbase + (unsigned)ss * QK_STAGE_U * 4;
        const unsigned kdst = qdst + 2048 * 4;
        #pragma unroll
        for (int t = 0; t < 2; t++) {
            const int idx = tid + t * 256;
            {
                const int qtl = idx >> 6, rem = idx & 63;
                const uint4* src = g_Qfr + ((size_t)(b * 128 + (q0 >> 4) + qtl) * 512
                                            + kt16 * 32 + rem);
                cp_async16(qdst + (unsigned)idx * 16, src);
            }
            {
                const int ntl = idx >> 5, rem = idx & 31;
                const uint2* src = g_Kfr + ((size_t)(b * 256 + (k0 >> 3) + ntl) * 512
                                            + kt16 * 32 + rem * 2);
                cp_async16(kdst + (unsigned)idx * 16, src);
            }
        }
    };

    load_stage(0, 0); CP_COMMIT();
    load_stage(1, 2); CP_COMMIT();
    load_stage(2, 4); CP_COMMIT();

    for (int i = 0; i < 8; i++) {
        CP_WAIT2();
        __syncthreads();
        if (i + 3 < 8) load_stage((i + 3) & 3, (i + 3) * 2);
        CP_COMMIT();

        const unsigned* Qst = smem_u + (i & 3) * QK_STAGE_U;
        const unsigned* Kst = Qst + 2048;

        #pragma unroll
        for (int ks = 0; ks < 2; ks++) {
            unsigned a[4][4], bb[4][2];
            #pragma unroll
            for (int mt = 0; mt < 4; mt++) {
                const uint4 q4 = *(const uint4*)(Qst + ((wmid * 4 + mt) * 2 + ks) * 128 + lane * 4);
                a[mt][0] = q4.x; a[mt][1] = q4.y; a[mt][2] = q4.z; a[mt][3] = q4.w;
            }
            #pragma unroll
            for (int nt = 0; nt < 4; nt++) {
                const uint2 k2 = *(const uint2*)(Kst + ((wnid * 4 + nt) * 2 + ks) * 64 + lane * 2);
                bb[nt][0] = k2.x; bb[nt][1] = k2.y;
            }
            #pragma unroll
            for (int mt = 0; mt < 4; mt++)
                #pragma unroll
                for (int nt = 0; nt < 4; nt++)
                    mma_bf16(acc[mt][nt], a[mt], bb[nt]);
        }
    }

    // Epilogue: exp -> fp16 quads; partial row sums.
    const float scale = (if_draw[0] != 0) ? (1.0f / 320.0f) : (1.0f / 16.0f);
    uint4* Eq = g_Ef + (size_t)(b * 16 + by) * 32768;

    #pragma unroll
    for (int mt = 0; mt < 4; mt++) {
        float slo = 0.f, shi = 0.f;
        const int r16 = wmid * 4 + mt;
        #pragma unroll
        for (int c = 0; c < 2; c++) {
            const int nt0 = 2 * c, nt1 = 2 * c + 1;
            float e00 = __expf(scale * acc[mt][nt0][0]);
            float e01 = __expf(scale * acc[mt][nt0][1]);
            float e02 = __expf(scale * acc[mt][nt0][2]);
            float e03 = __expf(scale * acc[mt][nt0][3]);
            float e10 = __expf(scale * acc[mt][nt1][0]);
            float e11 = __expf(scale * acc[mt][nt1][1]);
            float e12 = __expf(scale * acc[mt][nt1][2]);
            float e13 = __expf(scale * acc[mt][nt1][3]);
            slo += e00 + e01 + e10 + e11;
            shi += e02 + e03 + e12 + e13;
            uint4 q;
            q.x = pack_f16x2(e00, e01);
            q.y = pack_f16x2(e02, e03);
            q.z = pack_f16x2(e10, e11);
            q.w = pack_f16x2(e12, e13);
            const int kchunk = kx * 8 + wnid * 2 + c;
            Eq[(size_t)(r16 * 128 + kchunk) * 32 + lane] = q;
        }
        slo += __shfl_xor_sync(0xffffffffu, slo, 1);
        slo += __shfl_xor_sync(0xffffffffu, slo, 2);
        shi += __shfl_xor_sync(0xffffffffu, shi, 1);
        shi += __shfl_xor_sync(0xffffffffu, shi, 2);
        if (qd == 0) {
            const size_t rbase = (size_t)(b * L_ + q0 + wmid * 64 + mt * 16 + g) * 64 + kx * 4 + wnid;
            g_part[rbase]          = slo;
            g_part[rbase + 8 * 64] = shi;
        }
    }
}

// ---------------------------------------------------------------------------
// Kernel 2 (fp16 mma): O = (E @ V) * inv ; attn = fp32(E) * inv.
// One CTA per q-panel (full D=256), 512 threads, 6-stage cp.async pipeline.
// Row-sum reduction fused into the prologue (rowinv kernel deleted).
// ---------------------------------------------------------------------------
#define AV_STAGE_B 24576
#define AV_NSTAGE  6

__global__ __launch_bounds__(512, 1)
void av_f16_kernel(float* __restrict__ O,
                   float* __restrict__ attn) {
    extern __shared__ unsigned char smem_raw[];
    const unsigned sbase = (unsigned)__cvta_generic_to_shared(smem_raw);
    float* inv_s = (float*)(smem_raw + AV_NSTAGE * AV_STAGE_B);

    const int b  = blockIdx.y;
    const int qp = blockIdx.x;
    const int q0 = qp * 128;

    const uint4* Ab = g_Ef + (size_t)(b * 16 + qp) * 32768;
    const unsigned char* Vb = (const unsigned char*)(g_Vf + (size_t)b * 131072);

    const int tid  = threadIdx.x;
    const int lane = tid & 31;
    const int wid  = tid >> 5;
    const int wm16 = (wid & 1) * 4;
    const int ntb  = (wid >> 1) * 4;
    const int g    = lane >> 2;
    const int qd   = lane & 3;

    const int aw_r16 = tid >> 6;
    const int aw_kcl = (tid >> 5) & 1;
    const int aw_g   = (tid & 31) >> 2;
    const int aw_qd  = tid & 3;

    float acc[4][4][4] = {};

    auto load_stage = [&](int ss, int i) {
        const unsigned adst = sbase + (unsigned)ss * AV_STAGE_B;
        const unsigned vdst = adst + 8192;
        {
            const int r16 = tid >> 6, kcl = (tid >> 5) & 1, ln = tid & 31;
            cp_async16(adst + (unsigned)tid * 16,
                       Ab + (size_t)r16 * 4096 + (2 * i + kcl) * 32 + ln);
        }
        #pragma unroll
        for (int t = 0; t < 2; t++) {
            const int idx = tid + t * 512;
            cp_async16(vdst + (unsigned)idx * 16, Vb + (size_t)i * 16384 + idx * 16);
        }
    };

    #pragma unroll
    for (int s = 0; s < AV_NSTAGE - 1; s++) {
        load_stage(s, s);
        CP_COMMIT();
    }

    // Fused row-sum reduction: row = tid>>2, quarter = tid&3 (16 partials each).
    {
        const int row = tid >> 2, quar = tid & 3;
        const float* p = g_part + (size_t)(b * L_ + q0 + row) * 64 + quar * 16;
        float s = 0.f;
        #pragma unroll
        for (int t = 0; t < 16; t++) s += p[t];
        s += __shfl_xor_sync(0xffffffffu, s, 1);
        s += __shfl_xor_sync(0xffffffffu, s, 2);
        if (quar == 0) inv_s[row] = 1.0f / s;
    }

    float* attn_b = attn + (size_t)b * L_ * L_;

    for (int i = 0; i < 64; i++) {
        CP_WAIT4();
        __syncthreads();
        if (i + AV_NSTAGE - 1 < 64) load_stage((i + AV_NSTAGE - 1) % AV_NSTAGE, i + AV_NSTAGE - 1);
        CP_COMMIT();

        const unsigned char* Ast = smem_raw + (i % AV_NSTAGE) * AV_STAGE_B;
        const unsigned char* Vst = Ast + 8192;

        // attn = fp32(E) * inv : one quad per thread, contiguous float2 stores.
        {
            const uint4 q4 = *(const uint4*)(Ast + tid * 16);
            const int lr0 = aw_r16 * 16 + aw_g, lr1 = lr0 + 8;
            const float iv0 = inv_s[lr0], iv1 = inv_s[lr1];
            const int colb = i * 32 + aw_kcl * 16 + 2 * aw_qd;
            float2 p;
            float2 a0 = __half22float2(*(const __half2*)&q4.x);
            p.x = a0.x * iv0; p.y = a0.y * iv0;
            *(float2*)(attn_b + (size_t)(q0 + lr0) * L_ + colb) = p;
            float2 a1 = __half22float2(*(const __half2*)&q4.z);
            p.x = a1.x * iv0; p.y = a1.y * iv0;
            *(float2*)(attn_b + (size_t)(q0 + lr0) * L_ + colb + 8) = p;
            float2 a2 = __half22float2(*(const __half2*)&q4.y);
            p.x = a2.x * iv1; p.y = a2.y * iv1;
            *(float2*)(attn_b + (size_t)(q0 + lr1) * L_ + colb) = p;
            float2 a3 = __half22float2(*(const __half2*)&q4.w);
            p.x = a3.x * iv1; p.y = a3.y * iv1;
            *(float2*)(attn_b + (size_t)(q0 + lr1) * L_ + colb + 8) = p;
        }

        #pragma unroll
        for (int kc = 0; kc < 2; kc++) {
            unsigned a[4][4], bb[4][2];
            #pragma unroll
            for (int mt = 0; mt < 4; mt++) {
                const uint4 q4 = *(const uint4*)(Ast + (((wm16 + mt) * 2 + kc) * 32 + lane) * 16);
                a[mt][0] = q4.x; a[mt][1] = q4.y; a[mt][2] = q4.z; a[mt][3] = q4.w;
            }
            #pragma unroll
            for (int nt = 0; nt < 4; nt++) {
                const uint2 v2 = *(const uint2*)(Vst + (((kc * 32) + ntb + nt) * 32 + lane) * 8);
                bb[nt][0] = v2.x; bb[nt][1] = v2.y;
            }
            #pragma unroll
            for (int mt = 0; mt < 4; mt++)
                #pragma unroll
                for (int nt = 0; nt < 4; nt++)
                    mma_f16(acc[mt][nt], a[mt], bb[nt]);
        }
    }

    float* Ob = O + (size_t)b * L_ * D_;
    #pragma unroll
    for (int mt = 0; mt < 4; mt++) {
        const int lrow = (wid & 1) * 64 + mt * 16 + g;
        const int row  = q0 + lrow;
        const float iv0 = inv_s[lrow];
        const float iv1 = inv_s[lrow + 8];
        #pragma unroll
        for (int nt = 0; nt < 4; nt++) {
            const int col = (ntb + nt) * 8 + 2 * qd;
            float2 v0 = {acc[mt][nt][0] * iv0, acc[mt][nt][1] * iv0};
            float2 v1 = {acc[mt][nt][2] * iv1, acc[mt][nt][3] * iv1};
            *(float2*)(Ob + (size_t)row * D_ + col)       = v0;
            *(float2*)(Ob + (size_t)(row + 8) * D_ + col) = v1;
        }
    }
}

// ---------------------------------------------------------------------------
// Launch
// ---------------------------------------------------------------------------
extern "C" void kernel_launch(void* const* d_in, const int* in_sizes, int n_in,
                              void* d_out, int out_size) {
    const float* Q = (const float*)d_in[0];
    const float* K = (const float*)d_in[1];
    const float* V = (const float*)d_in[2];
    const int* if_draw = (const int*)d_in[4];

    float* out = (float*)d_out;

    const long long ctx_elems  = (long long)B_ * L_ * D_;
    const long long attn_elems = (long long)B_ * L_ * L_;

    float* Sptr;
    if ((long long)out_size >= ctx_elems + attn_elems)
        Sptr = out + ((long long)out_size - attn_elems);
    else
        Sptr = out + ctx_elems;

    static int attr_done = 0;
    const int qk_smem = QK_STAGE_U * 4 * 4;              // 65536 B
    const int av_smem = AV_STAGE_B * AV_NSTAGE + 512;    // 147968 B
    if (!attr_done) {
        cudaFuncSetAttribute(qk_exp_kernel, cudaFuncAttributeMaxDynamicSharedMemorySize, qk_smem);
        cudaFuncSetAttribute(av_f16_kernel, cudaFuncAttributeMaxDynamicSharedMemorySize, av_smem);
        attr_done = 1;
    }

    cvt_q_kernel<<<(B_ * 128 * 16 * 32) / 256, 256>>>(Q);
    cvt_k_kernel<<<(B_ * 256 * 16 * 32) / 256, 256>>>(K);
    cvt_v_f16<<<(B_ * 128 * 32 * 32) / 256, 256>>>(V);

    dim3 g1(L_ / 128, L_ / 128, B_);
    qk_exp_kernel<<<g1, 256, qk_smem>>>(if_draw);

    dim3 g2(16, B_);                    // (qpanel, b)
    av_f16_kernel<<<g2, 512, av_smem>>>(out, Sptr);
}

// round 14
// speedup vs baseline: 1.8082x; 1.0108x over previous
#include <cuda_runtime.h>
#include <cuda_bf16.h>
#include <cuda_fp16.h>

#define B_  16
#define L_  2048
#define D_  256

// Scratch (mma-fragment-major layouts):
//  g_Qfr : Q bf16 quads [b][qtile128][kchunk16][lane32] (uint4)  -- qk A frags
//  g_Kfr : K bf16 duos  [b][ntile256][kchunk16][lane32] (uint2)  -- qk B frags
//  g_Vf  : V fp16 duos  [b][kchunk128][ntile32][lane32] (uint2)  -- av B frags
//  g_Ef  : E fp16 quads [b*16+qp][r16 8][kchunk128][lane32] (uint4) -- av A frags
__device__ uint4  g_Qfr[(size_t)B_ * 128 * 16 * 32];
__device__ uint2  g_Kfr[(size_t)B_ * 256 * 16 * 32];
__device__ uint2  g_Vf[(size_t)B_ * 128 * 32 * 32];
__device__ uint4  g_Ef[(size_t)B_ * 16 * 8 * 128 * 32];
__device__ float  g_part[(size_t)B_ * L_ * 64];

__device__ __forceinline__ unsigned pack_bf16x2(float lo, float hi) {
    unsigned r;
    asm("cvt.rn.bf16x2.f32 %0, %1, %2;" : "=r"(r) : "f"(hi), "f"(lo));
    return r;
}
__device__ __forceinline__ unsigned pack_f16x2(float lo, float hi) {
    unsigned r;
    asm("cvt.rn.f16x2.f32 %0, %1, %2;" : "=r"(r) : "f"(hi), "f"(lo));
    return r;
}
__device__ __forceinline__ void mma_bf16(float* c, const unsigned* a, const unsigned* b) {
    asm volatile(
        "mma.sync.aligned.m16n8k16.row.col.f32.bf16.bf16.f32 "
        "{%0,%1,%2,%3}, {%4,%5,%6,%7}, {%8,%9}, {%0,%1,%2,%3};"
        : "+f"(c[0]), "+f"(c[1]), "+f"(c[2]), "+f"(c[3])
        : "r"(a[0]), "r"(a[1]), "r"(a[2]), "r"(a[3]), "r"(b[0]), "r"(b[1]));
}
__device__ __forceinline__ void mma_f16(float* c, const unsigned* a, const unsigned* b) {
    asm volatile(
        "mma.sync.aligned.m16n8k16.row.col.f32.f16.f16.f32 "
        "{%0,%1,%2,%3}, {%4,%5,%6,%7}, {%8,%9}, {%0,%1,%2,%3};"
        : "+f"(c[0]), "+f"(c[1]), "+f"(c[2]), "+f"(c[3])
        : "r"(a[0]), "r"(a[1]), "r"(a[2]), "r"(a[3]), "r"(b[0]), "r"(b[1]));
}
__device__ __forceinline__ void cp_async16(unsigned dst, const void* src) {
    asm volatile("cp.async.cg.shared.global [%0], [%1], 16;" :: "r"(dst), "l"(src));
}
// streaming stores for write-only outputs (keep L2 for the read streams)
__device__ __forceinline__ void stg_cs_f2(float* p, float x, float y) {
    asm volatile("st.global.cs.v2.f32 [%0], {%1,%2};" :: "l"(p), "f"(x), "f"(y) : "memory");
}
#define CP_COMMIT() asm volatile("cp.async.commit_group;" ::: "memory")
#define CP_WAIT2()  asm volatile("cp.async.wait_group 2;" ::: "memory")
#define CP_WAIT4()  asm volatile("cp.async.wait_group 4;" ::: "memory")

// ---------------------------------------------------------------------------
// Fused converter: Q quads | K duos | V duos, dispatched by block range.
// Q: 2^20 threads, K: 2^21, V: 2^21 (boundaries are block-aligned).
// ---------------------------------------------------------------------------
#define CVT_NQ (B_ * 128 * 16 * 32)           // 1,048,576
#define CVT_NK (B_ * 256 * 16 * 32)           // 2,097,152
#define CVT_NV (B_ * 128 * 32 * 32)           // 2,097,152

__global__ void cvt_all_kernel(const float* __restrict__ Q,
                               const float* __restrict__ K,
                               const float* __restrict__ V) {
    const int jj = blockIdx.x * 256 + threadIdx.x;
    if (jj < CVT_NQ) {
        const int j = jj;
        const int lane = j & 31, kc = (j >> 5) & 15, qt = (j >> 9) & 127, b = j >> 16;
        const int g = lane >> 2, qd = lane & 3;
        const float* base = Q + ((size_t)(b * L_) + qt * 16) * D_ + kc * 16 + qd * 2;
        const float2 r0a = *(const float2*)(base + (size_t)g * D_);
        const float2 r0b = *(const float2*)(base + (size_t)g * D_ + 8);
        const float2 r1a = *(const float2*)(base + (size_t)(g + 8) * D_);
        const float2 r1b = *(const float2*)(base + (size_t)(g + 8) * D_ + 8);
        uint4 out;
        out.x = pack_bf16x2(r0a.x, r0a.y);
        out.y = pack_bf16x2(r1a.x, r1a.y);
        out.z = pack_bf16x2(r0b.x, r0b.y);
        out.w = pack_bf16x2(r1b.x, r1b.y);
        g_Qfr[j] = out;
    } else if (jj < CVT_NQ + CVT_NK) {
        const int j = jj - CVT_NQ;
        const int lane = j & 31, kc = (j >> 5) & 15, nt = (j >> 9) & 255, b = j >> 17;
        const int g = lane >> 2, qd = lane & 3;
        const float* base = K + ((size_t)(b * L_) + nt * 8 + g) * D_ + kc * 16 + qd * 2;
        const float2 a = *(const float2*)(base);
        const float2 c = *(const float2*)(base + 8);
        uint2 out;
        out.x = pack_bf16x2(a.x, a.y);
        out.y = pack_bf16x2(c.x, c.y);
        g_Kfr[j] = out;
    } else {
        const int j = jj - CVT_NQ - CVT_NK;
        const int lane = j & 31, nt = (j >> 5) & 31, kc = (j >> 10) & 127, b = j >> 17;
        const int g = lane >> 2, qd = lane & 3;
        const float* Vb = V + (size_t)b * L_ * D_;
        const int col = nt * 8 + g;
        const int r0  = kc * 16 + 2 * qd;
        const float v00 = Vb[(size_t)r0 * D_ + col];
        const float v01 = Vb[(size_t)(r0 + 1) * D_ + col];
        const float v10 = Vb[(size_t)(r0 + 8) * D_ + col];
        const float v11 = Vb[(size_t)(r0 + 9) * D_ + col];
        uint2 out;
        out.x = pack_f16x2(v00, v01);
        out.y = pack_f16x2(v10, v11);
        g_Vf[j] = out;
    }
}

// ---------------------------------------------------------------------------
// Kernel 1: E = fp16(exp(scale * Q K^T)) quads + partial row sums.
// 4-stage cp.async pipeline (3 in flight).
// ---------------------------------------------------------------------------
#define QK_STAGE_U 4096

__global__ __launch_bounds__(256, 2)
void qk_exp_kernel(const int* __restrict__ if_draw) {
    extern __shared__ unsigned smem_u[];
    const unsigned sbase = (unsigned)__cvta_generic_to_shared(smem_u);

    const int b  = blockIdx.z;
    const int by = blockIdx.y;
    const int kx = blockIdx.x;
    const int q0 = by * 128;
    const int k0 = kx * 128;

    const int tid  = threadIdx.x;
    const int lane = tid & 31;
    const int wid  = tid >> 5;
    const int wmid = wid & 1;
    const int wnid = wid >> 1;
    const int g    = lane >> 2;
    const int qd   = lane & 3;

    float acc[4][4][4] = {};

    auto load_stage = [&](int ss, int kt16) {
        const unsigned qdst = sbase + (unsigned)ss * QK_STAGE_U * 4;
        const unsigned kdst = qdst + 2048 * 4;
        #pragma unroll
        for (int t = 0; t < 2; t++) {
            const int idx = tid + t * 256;
            {
                const int qtl = idx >> 6, rem = idx & 63;
                const uint4* src = g_Qfr + ((size_t)(b * 128 + (q0 >> 4) + qtl) * 512
                                            + kt16 * 32 + rem);
                cp_async16(qdst + (unsigned)idx * 16, src);
            }
            {
                const int ntl = idx >> 5, rem = idx & 31;
                const uint2* src = g_Kfr + ((size_t)(b * 256 + (k0 >> 3) + ntl) * 512
                                            + kt16 * 32 + rem * 2);
                cp_async16(kdst + (unsigned)idx * 16, src);
            }
        }
    };

    load_stage(0, 0); CP_COMMIT();
    load_stage(1, 2); CP_COMMIT();
    load_stage(2, 4); CP_COMMIT();

    for (int i = 0; i < 8; i++) {
        CP_WAIT2();
        __syncthreads();
        if (i + 3 < 8) load_stage((i + 3) & 3, (i + 3) * 2);
        CP_COMMIT();

        const unsigned* Qst = smem_u + (i & 3) * QK_STAGE_U;
        const unsigned* Kst = Qst + 2048;

        #pragma unroll
        for (int ks = 0; ks < 2; ks++) {
            unsigned a[4][4], bb[4][2];
            #pragma unroll
            for (int mt = 0; mt < 4; mt++) {
                const uint4 q4 = *(const uint4*)(Qst + ((wmid * 4 + mt) * 2 + ks) * 128 + lane * 4);
                a[mt][0] = q4.x; a[mt][1] = q4.y; a[mt][2] = q4.z; a[mt][3] = q4.w;
            }
            #pragma unroll
            for (int nt = 0; nt < 4; nt++) {
                const uint2 k2 = *(const uint2*)(Kst + ((wnid * 4 + nt) * 2 + ks) * 64 + lane * 2);
                bb[nt][0] = k2.x; bb[nt][1] = k2.y;
            }
            #pragma unroll
            for (int mt = 0; mt < 4; mt++)
                #pragma unroll
                for (int nt = 0; nt < 4; nt++)
                    mma_bf16(acc[mt][nt], a[mt], bb[nt]);
        }
    }

    // Epilogue: exp -> fp16 quads; partial row sums.
    const float scale = (if_draw[0] != 0) ? (1.0f / 320.0f) : (1.0f / 16.0f);
    uint4* Eq = g_Ef + (size_t)(b * 16 + by) * 32768;

    #pragma unroll
    for (int mt = 0; mt < 4; mt++) {
        float slo = 0.f, shi = 0.f;
        const int r16 = wmid * 4 + mt;
        #pragma unroll
        for (int c = 0; c < 2; c++) {
            const int nt0 = 2 * c, nt1 = 2 * c + 1;
            float e00 = __expf(scale * acc[mt][nt0][0]);
            float e01 = __expf(scale * acc[mt][nt0][1]);
            float e02 = __expf(scale * acc[mt][nt0][2]);
            float e03 = __expf(scale * acc[mt][nt0][3]);
            float e10 = __expf(scale * acc[mt][nt1][0]);
            float e11 = __expf(scale * acc[mt][nt1][1]);
            float e12 = __expf(scale * acc[mt][nt1][2]);
            float e13 = __expf(scale * acc[mt][nt1][3]);
            slo += e00 + e01 + e10 + e11;
            shi += e02 + e03 + e12 + e13;
            uint4 q;
            q.x = pack_f16x2(e00, e01);
            q.y = pack_f16x2(e02, e03);
            q.z = pack_f16x2(e10, e11);
            q.w = pack_f16x2(e12, e13);
            const int kchunk = kx * 8 + wnid * 2 + c;
            Eq[(size_t)(r16 * 128 + kchunk) * 32 + lane] = q;
        }
        slo += __shfl_xor_sync(0xffffffffu, slo, 1);
        slo += __shfl_xor_sync(0xffffffffu, slo, 2);
        shi += __shfl_xor_sync(0xffffffffu, shi, 1);
        shi += __shfl_xor_sync(0xffffffffu, shi, 2);
        if (qd == 0) {
            const size_t rbase = (size_t)(b * L_ + q0 + wmid * 64 + mt * 16 + g) * 64 + kx * 4 + wnid;
            g_part[rbase]          = slo;
            g_part[rbase + 8 * 64] = shi;
        }
    }
}

// ---------------------------------------------------------------------------
// Kernel 2 (fp16 mma): O = (E @ V) * inv ; attn = fp32(E) * inv.
// One CTA per q-panel (full D=256), 512 threads, 6-stage cp.async pipeline.
// mma issued first each iteration; attn streaming-stores follow.
// ---------------------------------------------------------------------------
#define AV_STAGE_B 24576
#define AV_NSTAGE  6

__global__ __launch_bounds__(512, 1)
void av_f16_kernel(float* __restrict__ O,
                   float* __restrict__ attn) {
    extern __shared__ unsigned char smem_raw[];
    const unsigned sbase = (unsigned)__cvta_generic_to_shared(smem_raw);
    float* inv_s = (float*)(smem_raw + AV_NSTAGE * AV_STAGE_B);

    const int b  = blockIdx.y;
    const int qp = blockIdx.x;
    const int q0 = qp * 128;

    const uint4* Ab = g_Ef + (size_t)(b * 16 + qp) * 32768;
    const unsigned char* Vb = (const unsigned char*)(g_Vf + (size_t)b * 131072);

    const int tid  = threadIdx.x;
    const int lane = tid & 31;
    const int wid  = tid >> 5;
    const int wm16 = (wid & 1) * 4;
    const int ntb  = (wid >> 1) * 4;
    const int g    = lane >> 2;
    const int qd   = lane & 3;

    const int aw_r16 = tid >> 6;
    const int aw_kcl = (tid >> 5) & 1;
    const int aw_g   = (tid & 31) >> 2;
    const int aw_qd  = tid & 3;

    float acc[4][4][4] = {};

    auto load_stage = [&](int ss, int i) {
        const unsigned adst = sbase + (unsigned)ss * AV_STAGE_B;
        const unsigned vdst = adst + 8192;
        {
            const int r16 = tid >> 6, kcl = (tid >> 5) & 1, ln = tid & 31;
            cp_async16(adst + (unsigned)tid * 16,
                       Ab + (size_t)r16 * 4096 + (2 * i + kcl) * 32 + ln);
        }
        #pragma unroll
        for (int t = 0; t < 2; t++) {
            const int idx = tid + t * 512;
            cp_async16(vdst + (unsigned)idx * 16, Vb + (size_t)i * 16384 + idx * 16);
        }
    };

    #pragma unroll
    for (int s = 0; s < AV_NSTAGE - 1; s++) {
        load_stage(s, s);
        CP_COMMIT();
    }

    // Fused row-sum reduction: row = tid>>2, quarter = tid&3 (16 partials each).
    {
        const int row = tid >> 2, quar = tid & 3;
        const float* p = g_part + (size_t)(b * L_ + q0 + row) * 64 + quar * 16;
        float s = 0.f;
        #pragma unroll
        for (int t = 0; t < 16; t++) s += p[t];
        s += __shfl_xor_sync(0xffffffffu, s, 1);
        s += __shfl_xor_sync(0xffffffffu, s, 2);
        if (quar == 0) inv_s[row] = 1.0f / s;
    }

    float* attn_b = attn + (size_t)b * L_ * L_;

    for (int i = 0; i < 64; i++) {
        CP_WAIT4();
        __syncthreads();
        if (i + AV_NSTAGE - 1 < 64) load_stage((i + AV_NSTAGE - 1) % AV_NSTAGE, i + AV_NSTAGE - 1);
        CP_COMMIT();

        const unsigned char* Ast = smem_raw + (i % AV_NSTAGE) * AV_STAGE_B;
        const unsigned char* Vst = Ast + 8192;

        // mma first — tensor pipe gets issue priority at stage start.
        #pragma unroll
        for (int kc = 0; kc < 2; kc++) {
            unsigned a[4][4], bb[4][2];
            #pragma unroll
            for (int mt = 0; mt < 4; mt++) {
                const uint4 q4 = *(const uint4*)(Ast + (((wm16 + mt) * 2 + kc) * 32 + lane) * 16);
                a[mt][0] = q4.x; a[mt][1] = q4.y; a[mt][2] = q4.z; a[mt][3] = q4.w;
            }
            #pragma unroll
            for (int nt = 0; nt < 4; nt++) {
                const uint2 v2 = *(const uint2*)(Vst + (((kc * 32) + ntb + nt) * 32 + lane) * 8);
                bb[nt][0] = v2.x; bb[nt][1] = v2.y;
            }
            #pragma unroll
            for (int mt = 0; mt < 4; mt++)
                #pragma unroll
                for (int nt = 0; nt < 4; nt++)
                    mma_f16(acc[mt][nt], a[mt], bb[nt]);
        }

        // attn = fp32(E) * inv — streaming stores (write-only output).
        {
            const uint4 q4 = *(const uint4*)(Ast + tid * 16);
            const int lr0 = aw_r16 * 16 + aw_g, lr1 = lr0 + 8;
            const float iv0 = inv_s[lr0], iv1 = inv_s[lr1];
            const int colb = i * 32 + aw_kcl * 16 + 2 * aw_qd;
            float2 a0 = __half22float2(*(const __half2*)&q4.x);
            stg_cs_f2(attn_b + (size_t)(q0 + lr0) * L_ + colb,     a0.x * iv0, a0.y * iv0);
            float2 a1 = __half22float2(*(const __half2*)&q4.z);
            stg_cs_f2(attn_b + (size_t)(q0 + lr0) * L_ + colb + 8, a1.x * iv0, a1.y * iv0);
            float2 a2 = __half22float2(*(const __half2*)&q4.y);
            stg_cs_f2(attn_b + (size_t)(q0 + lr1) * L_ + colb,     a2.x * iv1, a2.y * iv1);
            float2 a3 = __half22float2(*(const __half2*)&q4.w);
            stg_cs_f2(attn_b + (size_t)(q0 + lr1) * L_ + colb + 8, a3.x * iv1, a3.y * iv1);
        }
    }

    float* Ob = O + (size_t)b * L_ * D_;
    #pragma unroll
    for (int mt = 0; mt < 4; mt++) {
        const int lrow = (wid & 1) * 64 + mt * 16 + g;
        const int row  = q0 + lrow;
        const float iv0 = inv_s[lrow];
        const float iv1 = inv_s[lrow + 8];
        #pragma unroll
        for (int nt = 0; nt < 4; nt++) {
            const int col = (ntb + nt) * 8 + 2 * qd;
            stg_cs_f2(Ob + (size_t)row * D_ + col,
                      acc[mt][nt][0] * iv0, acc[mt][nt][1] * iv0);
            stg_cs_f2(Ob + (size_t)(row + 8) * D_ + col,
                      acc[mt][nt][2] * iv1, acc[mt][nt][3] * iv1);
        }
    }
}

// ---------------------------------------------------------------------------
// Launch
// ---------------------------------------------------------------------------
extern "C" void kernel_launch(void* const* d_in, const int* in_sizes, int n_in,
                              void* d_out, int out_size) {
    const float* Q = (const float*)d_in[0];
    const float* K = (const float*)d_in[1];
    const float* V = (const float*)d_in[2];
    const int* if_draw = (const int*)d_in[4];

    float* out = (float*)d_out;

    const long long ctx_elems  = (long long)B_ * L_ * D_;
    const long long attn_elems = (long long)B_ * L_ * L_;

    float* Sptr;
    if ((long long)out_size >= ctx_elems + attn_elems)
        Sptr = out + ((long long)out_size - attn_elems);
    else
        Sptr = out + ctx_elems;

    static int attr_done = 0;
    const int qk_smem = QK_STAGE_U * 4 * 4;              // 65536 B
    const int av_smem = AV_STAGE_B * AV_NSTAGE + 512;    // 147968 B
    if (!attr_done) {
        cudaFuncSetAttribute(qk_exp_kernel, cudaFuncAttributeMaxDynamicSharedMemorySize, qk_smem);
        cudaFuncSetAttribute(av_f16_kernel, cudaFuncAttributeMaxDynamicSharedMemorySize, av_smem);
        attr_done = 1;
    }

    cvt_all_kernel<<<(CVT_NQ + CVT_NK + CVT_NV) / 256, 256>>>(Q, K, V);

    dim3 g1(L_ / 128, L_ / 128, B_);
    qk_exp_kernel<<<g1, 256, qk_smem>>>(if_draw);

    dim3 g2(16, B_);                    // (qpanel, b)
    av_f16_kernel<<<g2, 512, av_smem>>>(out, Sptr);
}

// round 15
// speedup vs baseline: 1.8808x; 1.0401x over previous
#include <cuda_runtime.h>
#include <cuda_bf16.h>
#include <cuda_fp16.h>

#define B_  16
#define L_  2048
#define D_  256

// Scratch (mma-fragment-major layouts):
//  g_Qfr : Q bf16 quads [b][qtile128][kchunk16][lane32] (uint4)  -- qk A frags
//  g_Kfr : K bf16 duos  [b][ntile256][kchunk16][lane32] (uint2)  -- qk B frags
//  g_Vf  : V fp16 duos  [b][kchunk128][ntile32][lane32] (uint2)  -- av B frags
//  g_Ef  : E fp16 quads [b*16+qp][r16 8][kchunk128][lane32] (uint4) -- av A frags
__device__ uint4  g_Qfr[(size_t)B_ * 128 * 16 * 32];
__device__ uint2  g_Kfr[(size_t)B_ * 256 * 16 * 32];
__device__ uint2  g_Vf[(size_t)B_ * 128 * 32 * 32];
__device__ uint4  g_Ef[(size_t)B_ * 16 * 8 * 128 * 32];
__device__ float  g_part[(size_t)B_ * L_ * 64];

__device__ __forceinline__ unsigned pack_bf16x2(float lo, float hi) {
    unsigned r;
    asm("cvt.rn.bf16x2.f32 %0, %1, %2;" : "=r"(r) : "f"(hi), "f"(lo));
    return r;
}
__device__ __forceinline__ unsigned pack_f16x2(float lo, float hi) {
    unsigned r;
    asm("cvt.rn.f16x2.f32 %0, %1, %2;" : "=r"(r) : "f"(hi), "f"(lo));
    return r;
}
__device__ __forceinline__ void mma_bf16(float* c, const unsigned* a, const unsigned* b) {
    asm volatile(
        "mma.sync.aligned.m16n8k16.row.col.f32.bf16.bf16.f32 "
        "{%0,%1,%2,%3}, {%4,%5,%6,%7}, {%8,%9}, {%0,%1,%2,%3};"
        : "+f"(c[0]), "+f"(c[1]), "+f"(c[2]), "+f"(c[3])
        : "r"(a[0]), "r"(a[1]), "r"(a[2]), "r"(a[3]), "r"(b[0]), "r"(b[1]));
}
__device__ __forceinline__ void mma_f16(float* c, const unsigned* a, const unsigned* b) {
    asm volatile(
        "mma.sync.aligned.m16n8k16.row.col.f32.f16.f16.f32 "
        "{%0,%1,%2,%3}, {%4,%5,%6,%7}, {%8,%9}, {%0,%1,%2,%3};"
        : "+f"(c[0]), "+f"(c[1]), "+f"(c[2]), "+f"(c[3])
        : "r"(a[0]), "r"(a[1]), "r"(a[2]), "r"(a[3]), "r"(b[0]), "r"(b[1]));
}
__device__ __forceinline__ void cp_async16(unsigned dst, const void* src) {
    asm volatile("cp.async.cg.shared.global [%0], [%1], 16;" :: "r"(dst), "l"(src));
}
__device__ __forceinline__ void stg_cs_f2(float* p, float x, float y) {
    asm volatile("st.global.cs.v2.f32 [%0], {%1,%2};" :: "l"(p), "f"(x), "f"(y) : "memory");
}
__device__ __forceinline__ void stg_cs_f4(float* p, float x, float y, float z, float w) {
    asm volatile("st.global.cs.v4.f32 [%0], {%1,%2,%3,%4};"
                 :: "l"(p), "f"(x), "f"(y), "f"(z), "f"(w) : "memory");
}
#define CP_COMMIT() asm volatile("cp.async.commit_group;" ::: "memory")
#define CP_WAIT2()  asm volatile("cp.async.wait_group 2;" ::: "memory")
#define CP_WAIT4()  asm volatile("cp.async.wait_group 4;" ::: "memory")

// ---------------------------------------------------------------------------
// Smem-staged converter: coalesced 16B loads AND coalesced fragment writes.
// Blocks 0..2047: Q (b, qtile16-rows); 2048..4095: K (b, 16-row group = 2 ntiles);
// 4096..6143: V (b, kchunk 16-rows).
// ---------------------------------------------------------------------------
__global__ void cvt_all_kernel(const float* __restrict__ Q,
                               const float* __restrict__ K,
                               const float* __restrict__ V) {
    __shared__ float sm[16][264];
    const int blk = blockIdx.x;
    const int tid = threadIdx.x;

    const float* src;
    if (blk < 2048)       src = Q + ((size_t)(blk >> 7) * L_ + (blk & 127) * 16) * D_;
    else if (blk < 4096)  src = K + ((size_t)((blk - 2048) >> 7) * L_ + ((blk - 2048) & 127) * 16) * D_;
    else                  src = V + ((size_t)((blk - 4096) >> 7) * L_ + ((blk - 4096) & 127) * 16) * D_;

    #pragma unroll
    for (int t = 0; t < 4; t++) {
        const int idx = tid + t * 256;
        const int r = idx >> 6, c4 = (idx & 63) * 4;
        *(float4*)&sm[r][c4] = *(const float4*)(src + (size_t)r * D_ + c4);
    }
    __syncthreads();

    if (blk < 2048) {
        const int b = blk >> 7, qt = blk & 127;
        #pragma unroll
        for (int t = 0; t < 2; t++) {
            const int q = tid + t * 256;              // 512 quads
            const int kc = q >> 5, lane = q & 31;
            const int g = lane >> 2, qd = lane & 3;
            const int c = kc * 16 + qd * 2;
            uint4 o;
            o.x = pack_bf16x2(sm[g][c],         sm[g][c + 1]);
            o.y = pack_bf16x2(sm[g + 8][c],     sm[g + 8][c + 1]);
            o.z = pack_bf16x2(sm[g][c + 8],     sm[g][c + 9]);
            o.w = pack_bf16x2(sm[g + 8][c + 8], sm[g + 8][c + 9]);
            g_Qfr[((size_t)(b * 128 + qt) * 16 + kc) * 32 + lane] = o;
        }
    } else if (blk < 4096) {
        const int j = blk - 2048;
        const int b = j >> 7, blk16 = j & 127;
        #pragma unroll
        for (int t = 0; t < 4; t++) {
            const int q = tid + t * 256;              // 1024 duos (2 ntiles)
            const int ntl = q >> 9, kc = (q >> 5) & 15, lane = q & 31;
            const int g = lane >> 2, qd = lane & 3;
            const int r = ntl * 8 + g, c = kc * 16 + qd * 2;
            uint2 o;
            o.x = pack_bf16x2(sm[r][c],     sm[r][c + 1]);
            o.y = pack_bf16x2(sm[r][c + 8], sm[r][c + 9]);
            const int nt = blk16 * 2 + ntl;
            g_Kfr[((size_t)(b * 256 + nt) * 16 + kc) * 32 + lane] = o;
        }
    } else {
        const int j = blk - 4096;
        const int b = j >> 7, kc = j & 127;
        #pragma unroll
        for (int t = 0; t < 4; t++) {
            const int q = tid + t * 256;              // 1024 duos (32 ntiles)
            const int nt = q >> 5, lane = q & 31;
            const int g = lane >> 2, qd = lane & 3;
            const int col = nt * 8 + g, r0 = 2 * qd;
            uint2 o;
            o.x = pack_f16x2(sm[r0][col],     sm[r0 + 1][col]);
            o.y = pack_f16x2(sm[r0 + 8][col], sm[r0 + 9][col]);
            g_Vf[((size_t)(b * 128 + kc) * 32 + nt) * 32 + lane] = o;
        }
    }
}

// ---------------------------------------------------------------------------
// Kernel 1: E = fp16(exp(scale * Q K^T)) quads + partial row sums.
// 4-stage cp.async pipeline (3 in flight). Unchanged from R14.
// ---------------------------------------------------------------------------
#define QK_STAGE_U 4096

__global__ __launch_bounds__(256, 2)
void qk_exp_kernel(const int* __restrict__ if_draw) {
    extern __shared__ unsigned smem_u[];
    const unsigned sbase = (unsigned)__cvta_generic_to_shared(smem_u);

    const int b  = blockIdx.z;
    const int by = blockIdx.y;
    const int kx = blockIdx.x;
    const int q0 = by * 128;
    const int k0 = kx * 128;

    const int tid  = threadIdx.x;
    const int lane = tid & 31;
    const int wid  = tid >> 5;
    const int wmid = wid & 1;
    const int wnid = wid >> 1;
    const int g    = lane >> 2;
    const int qd   = lane & 3;

    float acc[4][4][4] = {};

    auto load_stage = [&](int ss, int kt16) {
        const unsigned qdst = sbase + (unsigned)ss * QK_STAGE_U * 4;
        const unsigned kdst = qdst + 2048 * 4;
        #pragma unroll
        for (int t = 0; t < 2; t++) {
            const int idx = tid + t * 256;
            {
                const int qtl = idx >> 6, rem = idx & 63;
                const uint4* src = g_Qfr + ((size_t)(b * 128 + (q0 >> 4) + qtl) * 512
                                            + kt16 * 32 + rem);
                cp_async16(qdst + (unsigned)idx * 16, src);
            }
            {
                const int ntl = idx >> 5, rem = idx & 31;
                const uint2* src = g_Kfr + ((size_t)(b * 256 + (k0 >> 3) + ntl) * 512
                                            + kt16 * 32 + rem * 2);
                cp_async16(kdst + (unsigned)idx * 16, src);
            }
        }
    };

    load_stage(0, 0); CP_COMMIT();
    load_stage(1, 2); CP_COMMIT();
    load_stage(2, 4); CP_COMMIT();

    for (int i = 0; i < 8; i++) {
        CP_WAIT2();
        __syncthreads();
        if (i + 3 < 8) load_stage((i + 3) & 3, (i + 3) * 2);
        CP_COMMIT();

        const unsigned* Qst = smem_u + (i & 3) * QK_STAGE_U;
        const unsigned* Kst = Qst + 2048;

        #pragma unroll
        for (int ks = 0; ks < 2; ks++) {
            unsigned a[4][4], bb[4][2];
            #pragma unroll
            for (int mt = 0; mt < 4; mt++) {
                const uint4 q4 = *(const uint4*)(Qst + ((wmid * 4 + mt) * 2 + ks) * 128 + lane * 4);
                a[mt][0] = q4.x; a[mt][1] = q4.y; a[mt][2] = q4.z; a[mt][3] = q4.w;
            }
            #pragma unroll
            for (int nt = 0; nt < 4; nt++) {
                const uint2 k2 = *(const uint2*)(Kst + ((wnid * 4 + nt) * 2 + ks) * 64 + lane * 2);
                bb[nt][0] = k2.x; bb[nt][1] = k2.y;
            }
            #pragma unroll
            for (int mt = 0; mt < 4; mt++)
                #pragma unroll
                for (int nt = 0; nt < 4; nt++)
                    mma_bf16(acc[mt][nt], a[mt], bb[nt]);
        }
    }

    const float scale = (if_draw[0] != 0) ? (1.0f / 320.0f) : (1.0f / 16.0f);
    uint4* Eq = g_Ef + (size_t)(b * 16 + by) * 32768;

    #pragma unroll
    for (int mt = 0; mt < 4; mt++) {
        float slo = 0.f, shi = 0.f;
        const int r16 = wmid * 4 + mt;
        #pragma unroll
        for (int c = 0; c < 2; c++) {
            const int nt0 = 2 * c, nt1 = 2 * c + 1;
            float e00 = __expf(scale * acc[mt][nt0][0]);
            float e01 = __expf(scale * acc[mt][nt0][1]);
            float e02 = __expf(scale * acc[mt][nt0][2]);
            float e03 = __expf(scale * acc[mt][nt0][3]);
            float e10 = __expf(scale * acc[mt][nt1][0]);
            float e11 = __expf(scale * acc[mt][nt1][1]);
            float e12 = __expf(scale * acc[mt][nt1][2]);
            float e13 = __expf(scale * acc[mt][nt1][3]);
            slo += e00 + e01 + e10 + e11;
            shi += e02 + e03 + e12 + e13;
            uint4 q;
            q.x = pack_f16x2(e00, e01);
            q.y = pack_f16x2(e02, e03);
            q.z = pack_f16x2(e10, e11);
            q.w = pack_f16x2(e12, e13);
            const int kchunk = kx * 8 + wnid * 2 + c;
            Eq[(size_t)(r16 * 128 + kchunk) * 32 + lane] = q;
        }
        slo += __shfl_xor_sync(0xffffffffu, slo, 1);
        slo += __shfl_xor_sync(0xffffffffu, slo, 2);
        shi += __shfl_xor_sync(0xffffffffu, shi, 1);
        shi += __shfl_xor_sync(0xffffffffu, shi, 2);
        if (qd == 0) {
            const size_t rbase = (size_t)(b * L_ + q0 + wmid * 64 + mt * 16 + g) * 64 + kx * 4 + wnid;
            g_part[rbase]          = slo;
            g_part[rbase + 8 * 64] = shi;
        }
    }
}

// ---------------------------------------------------------------------------
// Kernel 2 (fp16 mma): O = (E @ V) * inv ; attn = fp32(E) * inv.
// 6-stage pipeline; attn stores widened to 16B via lane-pair shfl exchange.
// ---------------------------------------------------------------------------
#define AV_STAGE_B 24576
#define AV_NSTAGE  6

__global__ __launch_bounds__(512, 1)
void av_f16_kernel(float* __restrict__ O,
                   float* __restrict__ attn) {
    extern __shared__ unsigned char smem_raw[];
    const unsigned sbase = (unsigned)__cvta_generic_to_shared(smem_raw);
    float* inv_s = (float*)(smem_raw + AV_NSTAGE * AV_STAGE_B);

    const int b  = blockIdx.y;
    const int qp = blockIdx.x;
    const int q0 = qp * 128;

    const uint4* Ab = g_Ef + (size_t)(b * 16 + qp) * 32768;
    const unsigned char* Vb = (const unsigned char*)(g_Vf + (size_t)b * 131072);

    const int tid  = threadIdx.x;
    const int lane = tid & 31;
    const int wid  = tid >> 5;
    const int wm16 = (wid & 1) * 4;
    const int ntb  = (wid >> 1) * 4;
    const int g    = lane >> 2;
    const int qd   = lane & 3;

    const int aw_r16 = tid >> 6;
    const int aw_kcl = (tid >> 5) & 1;
    const int aw_g   = (tid & 31) >> 2;
    const int aw_qd  = tid & 3;
    const int aw_odd = aw_qd & 1;
    const int aw_cb0 = aw_kcl * 16 + 4 * (aw_qd >> 1) + aw_odd * 8;

    float acc[4][4][4] = {};

    auto load_stage = [&](int ss, int i) {
        const unsigned adst = sbase + (unsigned)ss * AV_STAGE_B;
        const unsigned vdst = adst + 8192;
        {
            const int r16 = tid >> 6, kcl = (tid >> 5) & 1, ln = tid & 31;
            cp_async16(adst + (unsigned)tid * 16,
                       Ab + (size_t)r16 * 4096 + (2 * i + kcl) * 32 + ln);
        }
        #pragma unroll
        for (int t = 0; t < 2; t++) {
            const int idx = tid + t * 512;
            cp_async16(vdst + (unsigned)idx * 16, Vb + (size_t)i * 16384 + idx * 16);
        }
    };

    #pragma unroll
    for (int s = 0; s < AV_NSTAGE - 1; s++) {
        load_stage(s, s);
        CP_COMMIT();
    }

    // Fused row-sum reduction: row = tid>>2, quarter = tid&3 (16 partials each).
    {
        const int row = tid >> 2, quar = tid & 3;
        const float* p = g_part + (size_t)(b * L_ + q0 + row) * 64 + quar * 16;
        float s = 0.f;
        #pragma unroll
        for (int t = 0; t < 16; t++) s += p[t];
        s += __shfl_xor_sync(0xffffffffu, s, 1);
        s += __shfl_xor_sync(0xffffffffu, s, 2);
        if (quar == 0) inv_s[row] = 1.0f / s;
    }

    float* attn_b = attn + (size_t)b * L_ * L_;

    for (int i = 0; i < 64; i++) {
        CP_WAIT4();
        __syncthreads();
        if (i + AV_NSTAGE - 1 < 64) load_stage((i + AV_NSTAGE - 1) % AV_NSTAGE, i + AV_NSTAGE - 1);
        CP_COMMIT();

        const unsigned char* Ast = smem_raw + (i % AV_NSTAGE) * AV_STAGE_B;
        const unsigned char* Vst = Ast + 8192;

        // mma first — tensor pipe gets issue priority at stage start.
        #pragma unroll
        for (int kc = 0; kc < 2; kc++) {
            unsigned a[4][4], bb[4][2];
            #pragma unroll
            for (int mt = 0; mt < 4; mt++) {
                const uint4 q4 = *(const uint4*)(Ast + (((wm16 + mt) * 2 + kc) * 32 + lane) * 16);
                a[mt][0] = q4.x; a[mt][1] = q4.y; a[mt][2] = q4.z; a[mt][3] = q4.w;
            }
            #pragma unroll
            for (int nt = 0; nt < 4; nt++) {
                const uint2 v2 = *(const uint2*)(Vst + (((kc * 32) + ntb + nt) * 32 + lane) * 8);
                bb[nt][0] = v2.x; bb[nt][1] = v2.y;
            }
            #pragma unroll
            for (int mt = 0; mt < 4; mt++)
                #pragma unroll
                for (int nt = 0; nt < 4; nt++)
                    mma_f16(acc[mt][nt], a[mt], bb[nt]);
        }

        // attn = fp32(E) * inv — lane-pair exchange -> two 16B streaming stores.
        {
            const uint4 q4 = *(const uint4*)(Ast + tid * 16);
            const unsigned px = __shfl_xor_sync(0xffffffffu, q4.x, 1);
            const unsigned py = __shfl_xor_sync(0xffffffffu, q4.y, 1);
            const unsigned pz = __shfl_xor_sync(0xffffffffu, q4.z, 1);
            const unsigned pw = __shfl_xor_sync(0xffffffffu, q4.w, 1);
            const unsigned r0a = aw_odd ? pz : q4.x;
            const unsigned r0b = aw_odd ? q4.z : px;
            const unsigned r1a = aw_odd ? pw : q4.y;
            const unsigned r1b = aw_odd ? q4.w : py;
            const int lr0 = aw_r16 * 16 + aw_g, lr1 = lr0 + 8;
            const float iv0 = inv_s[lr0], iv1 = inv_s[lr1];
            const int cb = i * 32 + aw_cb0;
            const float2 A0 = __half22float2(*(const __half2*)&r0a);
            const float2 B0 = __half22float2(*(const __half2*)&r0b);
            stg_cs_f4(attn_b + (size_t)(q0 + lr0) * L_ + cb,
                      A0.x * iv0, A0.y * iv0, B0.x * iv0, B0.y * iv0);
            const float2 A1 = __half22float2(*(const __half2*)&r1a);
            const float2 B1 = __half22float2(*(const __half2*)&r1b);
            stg_cs_f4(attn_b + (size_t)(q0 + lr1) * L_ + cb,
                      A1.x * iv1, A1.y * iv1, B1.x * iv1, B1.y * iv1);
        }
    }

    float* Ob = O + (size_t)b * L_ * D_;
    #pragma unroll
    for (int mt = 0; mt < 4; mt++) {
        const int lrow = (wid & 1) * 64 + mt * 16 + g;
        const int row  = q0 + lrow;
        const float iv0 = inv_s[lrow];
        const float iv1 = inv_s[lrow + 8];
        #pragma unroll
        for (int nt = 0; nt < 4; nt++) {
            const int col = (ntb + nt) * 8 + 2 * qd;
            stg_cs_f2(Ob + (size_t)row * D_ + col,
                      acc[mt][nt][0] * iv0, acc[mt][nt][1] * iv0);
            stg_cs_f2(Ob + (size_t)(row + 8) * D_ + col,
                      acc[mt][nt][2] * iv1, acc[mt][nt][3] * iv1);
        }
    }
}

// ---------------------------------------------------------------------------
// Launch
// ---------------------------------------------------------------------------
extern "C" void kernel_launch(void* const* d_in, const int* in_sizes, int n_in,
                              void* d_out, int out_size) {
    const float* Q = (const float*)d_in[0];
    const float* K = (const float*)d_in[1];
    const float* V = (const float*)d_in[2];
    const int* if_draw = (const int*)d_in[4];

    float* out = (float*)d_out;

    const long long ctx_elems  = (long long)B_ * L_ * D_;
    const long long attn_elems = (long long)B_ * L_ * L_;

    float* Sptr;
    if ((long long)out_size >= ctx_elems + attn_elems)
        Sptr = out + ((long long)out_size - attn_elems);
    else
        Sptr = out + ctx_elems;

    static int attr_done = 0;
    const int qk_smem = QK_STAGE_U * 4 * 4;              // 65536 B
    const int av_smem = AV_STAGE_B * AV_NSTAGE + 512;    // 147968 B
    if (!attr_done) {
        cudaFuncSetAttribute(qk_exp_kernel, cudaFuncAttributeMaxDynamicSharedMemorySize, qk_smem);
        cudaFuncSetAttribute(av_f16_kernel, cudaFuncAttributeMaxDynamicSharedMemorySize, av_smem);
        attr_done = 1;
    }

    cvt_all_kernel<<<6144, 256>>>(Q, K, V);

    dim3 g1(L_ / 128, L_ / 128, B_);
    qk_exp_kernel<<<g1, 256, qk_smem>>>(if_draw);

    dim3 g2(16, B_);                    // (qpanel, b)
    av_f16_kernel<<<g2, 512, av_smem>>>(out, Sptr);
}

// round 16
// speedup vs baseline: 1.8900x; 1.0049x over previous
#include <cuda_runtime.h>
#include <cuda_bf16.h>
#include <cuda_fp16.h>

#define B_  16
#define L_  2048
#define D_  256

// Scratch (mma-fragment-major layouts):
__device__ uint4  g_Qfr[(size_t)B_ * 128 * 16 * 32];
__device__ uint2  g_Kfr[(size_t)B_ * 256 * 16 * 32];
__device__ uint2  g_Vf[(size_t)B_ * 128 * 32 * 32];
__device__ uint4  g_Ef[(size_t)B_ * 16 * 8 * 128 * 32];
__device__ float  g_part[(size_t)B_ * L_ * 64];

__device__ __forceinline__ unsigned pack_bf16x2(float lo, float hi) {
    unsigned r;
    asm("cvt.rn.bf16x2.f32 %0, %1, %2;" : "=r"(r) : "f"(hi), "f"(lo));
    return r;
}
__device__ __forceinline__ unsigned pack_f16x2(float lo, float hi) {
    unsigned r;
    asm("cvt.rn.f16x2.f32 %0, %1, %2;" : "=r"(r) : "f"(hi), "f"(lo));
    return r;
}
__device__ __forceinline__ void mma_bf16(float* c, const unsigned* a, const unsigned* b) {
    asm volatile(
        "mma.sync.aligned.m16n8k16.row.col.f32.bf16.bf16.f32 "
        "{%0,%1,%2,%3}, {%4,%5,%6,%7}, {%8,%9}, {%0,%1,%2,%3};"
        : "+f"(c[0]), "+f"(c[1]), "+f"(c[2]), "+f"(c[3])
        : "r"(a[0]), "r"(a[1]), "r"(a[2]), "r"(a[3]), "r"(b[0]), "r"(b[1]));
}
__device__ __forceinline__ void mma_f16(float* c, const unsigned* a, const unsigned* b) {
    asm volatile(
        "mma.sync.aligned.m16n8k16.row.col.f32.f16.f16.f32 "
        "{%0,%1,%2,%3}, {%4,%5,%6,%7}, {%8,%9}, {%0,%1,%2,%3};"
        : "+f"(c[0]), "+f"(c[1]), "+f"(c[2]), "+f"(c[3])
        : "r"(a[0]), "r"(a[1]), "r"(a[2]), "r"(a[3]), "r"(b[0]), "r"(b[1]));
}
__device__ __forceinline__ void cp_async16(unsigned dst, const void* src) {
    asm volatile("cp.async.cg.shared.global [%0], [%1], 16;" :: "r"(dst), "l"(src));
}
__device__ __forceinline__ void stg_cs_f2(float* p, float x, float y) {
    asm volatile("st.global.cs.v2.f32 [%0], {%1,%2};" :: "l"(p), "f"(x), "f"(y) : "memory");
}
__device__ __forceinline__ void stg_cs_f4(float* p, float x, float y, float z, float w) {
    asm volatile("st.global.cs.v4.f32 [%0], {%1,%2,%3,%4};"
                 :: "l"(p), "f"(x), "f"(y), "f"(z), "f"(w) : "memory");
}
__device__ __forceinline__ void stg_cs_u4(void* p, uint4 v) {
    asm volatile("st.global.cs.v4.u32 [%0], {%1,%2,%3,%4};"
                 :: "l"(p), "r"(v.x), "r"(v.y), "r"(v.z), "r"(v.w) : "memory");
}
__device__ __forceinline__ void stg_cs_f1(float* p, float x) {
    asm volatile("st.global.cs.f32 [%0], %1;" :: "l"(p), "f"(x) : "memory");
}
#define CP_COMMIT() asm volatile("cp.async.commit_group;" ::: "memory")
#define CP_WAIT4()  asm volatile("cp.async.wait_group 4;" ::: "memory")
#define CP_WAIT6()  asm volatile("cp.async.wait_group 6;" ::: "memory")

// ---------------------------------------------------------------------------
// Smem-staged converter (unchanged R15).
// ---------------------------------------------------------------------------
__global__ void cvt_all_kernel(const float* __restrict__ Q,
                               const float* __restrict__ K,
                               const float* __restrict__ V) {
    __shared__ float sm[16][264];
    const int blk = blockIdx.x;
    const int tid = threadIdx.x;

    const float* src;
    if (blk < 2048)       src = Q + ((size_t)(blk >> 7) * L_ + (blk & 127) * 16) * D_;
    else if (blk < 4096)  src = K + ((size_t)((blk - 2048) >> 7) * L_ + ((blk - 2048) & 127) * 16) * D_;
    else                  src = V + ((size_t)((blk - 4096) >> 7) * L_ + ((blk - 4096) & 127) * 16) * D_;

    #pragma unroll
    for (int t = 0; t < 4; t++) {
        const int idx = tid + t * 256;
        const int r = idx >> 6, c4 = (idx & 63) * 4;
        *(float4*)&sm[r][c4] = *(const float4*)(src + (size_t)r * D_ + c4);
    }
    __syncthreads();

    if (blk < 2048) {
        const int b = blk >> 7, qt = blk & 127;
        #pragma unroll
        for (int t = 0; t < 2; t++) {
            const int q = tid + t * 256;
            const int kc = q >> 5, lane = q & 31;
            const int g = lane >> 2, qd = lane & 3;
            const int c = kc * 16 + qd * 2;
            uint4 o;
            o.x = pack_bf16x2(sm[g][c],         sm[g][c + 1]);
            o.y = pack_bf16x2(sm[g + 8][c],     sm[g + 8][c + 1]);
            o.z = pack_bf16x2(sm[g][c + 8],     sm[g][c + 9]);
            o.w = pack_bf16x2(sm[g + 8][c + 8], sm[g + 8][c + 9]);
            g_Qfr[((size_t)(b * 128 + qt) * 16 + kc) * 32 + lane] = o;
        }
    } else if (blk < 4096) {
        const int j = blk - 2048;
        const int b = j >> 7, blk16 = j & 127;
        #pragma unroll
        for (int t = 0; t < 4; t++) {
            const int q = tid + t * 256;
            const int ntl = q >> 9, kc = (q >> 5) & 15, lane = q & 31;
            const int g = lane >> 2, qd = lane & 3;
            const int r = ntl * 8 + g, c = kc * 16 + qd * 2;
            uint2 o;
            o.x = pack_bf16x2(sm[r][c],     sm[r][c + 1]);
            o.y = pack_bf16x2(sm[r][c + 8], sm[r][c + 9]);
            const int nt = blk16 * 2 + ntl;
            g_Kfr[((size_t)(b * 256 + nt) * 16 + kc) * 32 + lane] = o;
        }
    } else {
        const int j = blk - 4096;
        const int b = j >> 7, kc = j & 127;
        #pragma unroll
        for (int t = 0; t < 4; t++) {
            const int q = tid + t * 256;
            const int nt = q >> 5, lane = q & 31;
            const int g = lane >> 2, qd = lane & 3;
            const int col = nt * 8 + g, r0 = 2 * qd;
            uint2 o;
            o.x = pack_f16x2(sm[r0][col],     sm[r0 + 1][col]);
            o.y = pack_f16x2(sm[r0 + 8][col], sm[r0 + 9][col]);
            g_Vf[((size_t)(b * 128 + kc) * 32 + nt) * 32 + lane] = o;
        }
    }
}

// ---------------------------------------------------------------------------
// Kernel 1: E = fp16(exp(scale * Q K^T)) quads + partial row sums.
// 6-stage cp.async pipeline (5 in flight). E stores streaming (evict-first).
// ---------------------------------------------------------------------------
#define QK_STAGE_U 4096
#define QK_NSTAGE  6

__global__ __launch_bounds__(256, 2)
void qk_exp_kernel(const int* __restrict__ if_draw) {
    extern __shared__ unsigned smem_u[];
    const unsigned sbase = (unsigned)__cvta_generic_to_shared(smem_u);

    const int b  = blockIdx.z;
    const int by = blockIdx.y;
    const int kx = blockIdx.x;
    const int q0 = by * 128;
    const int k0 = kx * 128;

    const int tid  = threadIdx.x;
    const int lane = tid & 31;
    const int wid  = tid >> 5;
    const int wmid = wid & 1;
    const int wnid = wid >> 1;
    const int g    = lane >> 2;
    const int qd   = lane & 3;

    float acc[4][4][4] = {};

    auto load_stage = [&](int ss, int kt16) {
        const unsigned qdst = sbase + (unsigned)ss * QK_STAGE_U * 4;
        const unsigned kdst = qdst + 2048 * 4;
        #pragma unroll
        for (int t = 0; t < 2; t++) {
            const int idx = tid + t * 256;
            {
                const int qtl = idx >> 6, rem = idx & 63;
                const uint4* src = g_Qfr + ((size_t)(b * 128 + (q0 >> 4) + qtl) * 512
                                            + kt16 * 32 + rem);
                cp_async16(qdst + (unsigned)idx * 16, src);
            }
            {
                const int ntl = idx >> 5, rem = idx & 31;
                const uint2* src = g_Kfr + ((size_t)(b * 256 + (k0 >> 3) + ntl) * 512
                                            + kt16 * 32 + rem * 2);
                cp_async16(kdst + (unsigned)idx * 16, src);
            }
        }
    };

    #pragma unroll
    for (int s = 0; s < QK_NSTAGE - 1; s++) {
        load_stage(s, s * 2);
        CP_COMMIT();
    }

    for (int i = 0; i < 8; i++) {
        CP_WAIT4();
        __syncthreads();
        if (i + QK_NSTAGE - 1 < 8) load_stage((i + QK_NSTAGE - 1) % QK_NSTAGE, (i + QK_NSTAGE - 1) * 2);
        CP_COMMIT();

        const unsigned* Qst = smem_u + (i % QK_NSTAGE) * QK_STAGE_U;
        const unsigned* Kst = Qst + 2048;

        #pragma unroll
        for (int ks = 0; ks < 2; ks++) {
            unsigned a[4][4], bb[4][2];
            #pragma unroll
            for (int mt = 0; mt < 4; mt++) {
                const uint4 q4 = *(const uint4*)(Qst + ((wmid * 4 + mt) * 2 + ks) * 128 + lane * 4);
                a[mt][0] = q4.x; a[mt][1] = q4.y; a[mt][2] = q4.z; a[mt][3] = q4.w;
            }
            #pragma unroll
            for (int nt = 0; nt < 4; nt++) {
                const uint2 k2 = *(const uint2*)(Kst + ((wnid * 4 + nt) * 2 + ks) * 64 + lane * 2);
                bb[nt][0] = k2.x; bb[nt][1] = k2.y;
            }
            #pragma unroll
            for (int mt = 0; mt < 4; mt++)
                #pragma unroll
                for (int nt = 0; nt < 4; nt++)
                    mma_bf16(acc[mt][nt], a[mt], bb[nt]);
        }
    }

    const float scale = (if_draw[0] != 0) ? (1.0f / 320.0f) : (1.0f / 16.0f);
    uint4* Eq = g_Ef + (size_t)(b * 16 + by) * 32768;

    #pragma unroll
    for (int mt = 0; mt < 4; mt++) {
        float slo = 0.f, shi = 0.f;
        const int r16 = wmid * 4 + mt;
        #pragma unroll
        for (int c = 0; c < 2; c++) {
            const int nt0 = 2 * c, nt1 = 2 * c + 1;
            float e00 = __expf(scale * acc[mt][nt0][0]);
            float e01 = __expf(scale * acc[mt][nt0][1]);
            float e02 = __expf(scale * acc[mt][nt0][2]);
            float e03 = __expf(scale * acc[mt][nt0][3]);
            float e10 = __expf(scale * acc[mt][nt1][0]);
            float e11 = __expf(scale * acc[mt][nt1][1]);
            float e12 = __expf(scale * acc[mt][nt1][2]);
            float e13 = __expf(scale * acc[mt][nt1][3]);
            slo += e00 + e01 + e10 + e11;
            shi += e02 + e03 + e12 + e13;
            uint4 q;
            q.x = pack_f16x2(e00, e01);
            q.y = pack_f16x2(e02, e03);
            q.z = pack_f16x2(e10, e11);
            q.w = pack_f16x2(e12, e13);
            const int kchunk = kx * 8 + wnid * 2 + c;
            stg_cs_u4(&Eq[(size_t)(r16 * 128 + kchunk) * 32 + lane], q);
        }
        slo += __shfl_xor_sync(0xffffffffu, slo, 1);
        slo += __shfl_xor_sync(0xffffffffu, slo, 2);
        shi += __shfl_xor_sync(0xffffffffu, shi, 1);
        shi += __shfl_xor_sync(0xffffffffu, shi, 2);
        if (qd == 0) {
            const size_t rbase = (size_t)(b * L_ + q0 + wmid * 64 + mt * 16 + g) * 64 + kx * 4 + wnid;
            stg_cs_f1(&g_part[rbase], slo);
            stg_cs_f1(&g_part[rbase + 8 * 64], shi);
        }
    }
}

// ---------------------------------------------------------------------------
// Kernel 2 (fp16 mma): O = (E @ V) * inv ; attn = fp32(E) * inv.
// 8-stage pipeline (7 in flight); row-sum reduction hoisted before prologue.
// ---------------------------------------------------------------------------
#define AV_STAGE_B 24576
#define AV_NSTAGE  8

__global__ __launch_bounds__(512, 1)
void av_f16_kernel(float* __restrict__ O,
                   float* __restrict__ attn) {
    extern __shared__ unsigned char smem_raw[];
    const unsigned sbase = (unsigned)__cvta_generic_to_shared(smem_raw);
    float* inv_s = (float*)(smem_raw + AV_NSTAGE * AV_STAGE_B);

    const int b  = blockIdx.y;
    const int qp = blockIdx.x;
    const int q0 = qp * 128;

    const uint4* Ab = g_Ef + (size_t)(b * 16 + qp) * 32768;
    const unsigned char* Vb = (const unsigned char*)(g_Vf + (size_t)b * 131072);

    const int tid  = threadIdx.x;
    const int lane = tid & 31;
    const int wid  = tid >> 5;
    const int wm16 = (wid & 1) * 4;
    const int ntb  = (wid >> 1) * 4;
    const int g    = lane >> 2;
    const int qd   = lane & 3;

    const int aw_r16 = tid >> 6;
    const int aw_kcl = (tid >> 5) & 1;
    const int aw_g   = (tid & 31) >> 2;
    const int aw_qd  = tid & 3;
    const int aw_odd = aw_qd & 1;
    const int aw_cb0 = aw_kcl * 16 + 4 * (aw_qd >> 1) + aw_odd * 8;

    float acc[4][4][4] = {};

    // Row-sum partial loads issued FIRST: LDG latency overlaps the cp.async prologue.
    const int rs_row = tid >> 2, rs_q = tid & 3;
    float rs = 0.f;
    {
        const float* p = g_part + (size_t)(b * L_ + q0 + rs_row) * 64 + rs_q * 16;
        #pragma unroll
        for (int t = 0; t < 16; t += 4) {
            const float4 v = *(const float4*)(p + t);
            rs += (v.x + v.y) + (v.z + v.w);
        }
    }

    auto load_stage = [&](int ss, int i) {
        const unsigned adst = sbase + (unsigned)ss * AV_STAGE_B;
        const unsigned vdst = adst + 8192;
        {
            const int r16 = tid >> 6, kcl = (tid >> 5) & 1, ln = tid & 31;
            cp_async16(adst + (unsigned)tid * 16,
                       Ab + (size_t)r16 * 4096 + (2 * i + kcl) * 32 + ln);
        }
        #pragma unroll
        for (int t = 0; t < 2; t++) {
            const int idx = tid + t * 512;
            cp_async16(vdst + (unsigned)idx * 16, Vb + (size_t)i * 16384 + idx * 16);
        }
    };

    #pragma unroll
    for (int s = 0; s < AV_NSTAGE - 1; s++) {
        load_stage(s, s);
        CP_COMMIT();
    }

    // finish row-sum reduction
    rs += __shfl_xor_sync(0xffffffffu, rs, 1);
    rs += __shfl_xor_sync(0xffffffffu, rs, 2);
    if (rs_q == 0) inv_s[rs_row] = 1.0f / rs;

    float* attn_b = attn + (size_t)b * L_ * L_;

    for (int i = 0; i < 64; i++) {
        CP_WAIT6();
        __syncthreads();
        if (i + AV_NSTAGE - 1 < 64) load_stage((i + AV_NSTAGE - 1) % AV_NSTAGE, i + AV_NSTAGE - 1);
        CP_COMMIT();

        const unsigned char* Ast = smem_raw + (i % AV_NSTAGE) * AV_STAGE_B;
        const unsigned char* Vst = Ast + 8192;

        // mma first — tensor pipe gets issue priority at stage start.
        #pragma unroll
        for (int kc = 0; kc < 2; kc++) {
            unsigned a[4][4], bb[4][2];
            #pragma unroll
            for (int mt = 0; mt < 4; mt++) {
                const uint4 q4 = *(const uint4*)(Ast + (((wm16 + mt) * 2 + kc) * 32 + lane) * 16);
                a[mt][0] = q4.x; a[mt][1] = q4.y; a[mt][2] = q4.z; a[mt][3] = q4.w;
            }
            #pragma unroll
            for (int nt = 0; nt < 4; nt++) {
                const uint2 v2 = *(const uint2*)(Vst + (((kc * 32) + ntb + nt) * 32 + lane) * 8);
                bb[nt][0] = v2.x; bb[nt][1] = v2.y;
            }
            #pragma unroll
            for (int mt = 0; mt < 4; mt++)
                #pragma unroll
                for (int nt = 0; nt < 4; nt++)
                    mma_f16(acc[mt][nt], a[mt], bb[nt]);
        }

        // attn = fp32(E) * inv — lane-pair exchange -> two 16B streaming stores.
        {
            const uint4 q4 = *(const uint4*)(Ast + tid * 16);
            const unsigned px = __shfl_xor_sync(0xffffffffu, q4.x, 1);
            const unsigned py = __shfl_xor_sync(0xffffffffu, q4.y, 1);
            const unsigned pz = __shfl_xor_sync(0xffffffffu, q4.z, 1);
            const unsigned pw = __shfl_xor_sync(0xffffffffu, q4.w, 1);
            const unsigned r0a = aw_odd ? pz : q4.x;
            const unsigned r0b = aw_odd ? q4.z : px;
            const unsigned r1a = aw_odd ? pw : q4.y;
            const unsigned r1b = aw_odd ? q4.w : py;
            const int lr0 = aw_r16 * 16 + aw_g, lr1 = lr0 + 8;
            const float iv0 = inv_s[lr0], iv1 = inv_s[lr1];
            const int cb = i * 32 + aw_cb0;
            const float2 A0 = __half22float2(*(const __half2*)&r0a);
            const float2 B0 = __half22float2(*(const __half2*)&r0b);
            stg_cs_f4(attn_b + (size_t)(q0 + lr0) * L_ + cb,
                      A0.x * iv0, A0.y * iv0, B0.x * iv0, B0.y * iv0);
            const float2 A1 = __half22float2(*(const __half2*)&r1a);
            const float2 B1 = __half22float2(*(const __half2*)&r1b);
            stg_cs_f4(attn_b + (size_t)(q0 + lr1) * L_ + cb,
                      A1.x * iv1, A1.y * iv1, B1.x * iv1, B1.y * iv1);
        }
    }

    float* Ob = O + (size_t)b * L_ * D_;
    #pragma unroll
    for (int mt = 0; mt < 4; mt++) {
        const int lrow = (wid & 1) * 64 + mt * 16 + g;
        const int row  = q0 + lrow;
        const float iv0 = inv_s[lrow];
        const float iv1 = inv_s[lrow + 8];
        #pragma unroll
        for (int nt = 0; nt < 4; nt++) {
            const int col = (ntb + nt) * 8 + 2 * qd;
            stg_cs_f2(Ob + (size_t)row * D_ + col,
                      acc[mt][nt][0] * iv0, acc[mt][nt][1] * iv0);
            stg_cs_f2(Ob + (size_t)(row + 8) * D_ + col,
                      acc[mt][nt][2] * iv1, acc[mt][nt][3] * iv1);
        }
    }
}

// ---------------------------------------------------------------------------
// Launch
// ---------------------------------------------------------------------------
extern "C" void kernel_launch(void* const* d_in, const int* in_sizes, int n_in,
                              void* d_out, int out_size) {
    const float* Q = (const float*)d_in[0];
    const float* K = (const float*)d_in[1];
    const float* V = (const float*)d_in[2];
    const int* if_draw = (const int*)d_in[4];

    float* out = (float*)d_out;

    const long long ctx_elems  = (long long)B_ * L_ * D_;
    const long long attn_elems = (long long)B_ * L_ * L_;

    float* Sptr;
    if ((long long)out_size >= ctx_elems + attn_elems)
        Sptr = out + ((long long)out_size - attn_elems);
    else
        Sptr = out + ctx_elems;

    static int attr_done = 0;
    const int qk_smem = QK_STAGE_U * QK_NSTAGE * 4;      // 98304 B
    const int av_smem = AV_STAGE_B * AV_NSTAGE + 512;    // 197120 B
    if (!attr_done) {
        cudaFuncSetAttribute(qk_exp_kernel, cudaFuncAttributeMaxDynamicSharedMemorySize, qk_smem);
        cudaFuncSetAttribute(av_f16_kernel, cudaFuncAttributeMaxDynamicSharedMemorySize, av_smem);
        attr_done = 1;
    }

    cvt_all_kernel<<<6144, 256>>>(Q, K, V);

    dim3 g1(L_ / 128, L_ / 128, B_);
    qk_exp_kernel<<<g1, 256, qk_smem>>>(if_draw);

    dim3 g2(16, B_);                    // (qpanel, b)
    av_f16_kernel<<<g2, 512, av_smem>>>(out, Sptr);
}

// round 17
// speedup vs baseline: 1.9101x; 1.0107x over previous
#include <cuda_runtime.h>
#include <cuda_bf16.h>
#include <cuda_fp16.h>

#define B_  16
#define L_  2048
#define D_  256

// Scratch (mma-fragment-major layouts):
__device__ uint4  g_Qfr[(size_t)B_ * 128 * 16 * 32];
__device__ uint2  g_Kfr[(size_t)B_ * 256 * 16 * 32];
__device__ uint2  g_Vf[(size_t)B_ * 128 * 32 * 32];
__device__ uint4  g_Ef[(size_t)B_ * 16 * 8 * 128 * 32];
__device__ float  g_part[(size_t)B_ * L_ * 64];

__device__ __forceinline__ unsigned pack_bf16x2(float lo, float hi) {
    unsigned r;
    asm("cvt.rn.bf16x2.f32 %0, %1, %2;" : "=r"(r) : "f"(hi), "f"(lo));
    return r;
}
__device__ __forceinline__ unsigned pack_f16x2(float lo, float hi) {
    unsigned r;
    asm("cvt.rn.f16x2.f32 %0, %1, %2;" : "=r"(r) : "f"(hi), "f"(lo));
    return r;
}
__device__ __forceinline__ void mma_bf16(float* c, const unsigned* a, const unsigned* b) {
    asm volatile(
        "mma.sync.aligned.m16n8k16.row.col.f32.bf16.bf16.f32 "
        "{%0,%1,%2,%3}, {%4,%5,%6,%7}, {%8,%9}, {%0,%1,%2,%3};"
        : "+f"(c[0]), "+f"(c[1]), "+f"(c[2]), "+f"(c[3])
        : "r"(a[0]), "r"(a[1]), "r"(a[2]), "r"(a[3]), "r"(b[0]), "r"(b[1]));
}
__device__ __forceinline__ void mma_f16(float* c, const unsigned* a, const unsigned* b) {
    asm volatile(
        "mma.sync.aligned.m16n8k16.row.col.f32.f16.f16.f32 "
        "{%0,%1,%2,%3}, {%4,%5,%6,%7}, {%8,%9}, {%0,%1,%2,%3};"
        : "+f"(c[0]), "+f"(c[1]), "+f"(c[2]), "+f"(c[3])
        : "r"(a[0]), "r"(a[1]), "r"(a[2]), "r"(a[3]), "r"(b[0]), "r"(b[1]));
}
__device__ __forceinline__ void cp_async16(unsigned dst, const void* src) {
    asm volatile("cp.async.cg.shared.global [%0], [%1], 16;" :: "r"(dst), "l"(src));
}
__device__ __forceinline__ void stg_cs_f2(float* p, float x, float y) {
    asm volatile("st.global.cs.v2.f32 [%0], {%1,%2};" :: "l"(p), "f"(x), "f"(y) : "memory");
}
__device__ __forceinline__ void stg_cs_f4(float* p, float x, float y, float z, float w) {
    asm volatile("st.global.cs.v4.f32 [%0], {%1,%2,%3,%4};"
                 :: "l"(p), "f"(x), "f"(y), "f"(z), "f"(w) : "memory");
}
__device__ __forceinline__ void stg_cs_u4(void* p, uint4 v) {
    asm volatile("st.global.cs.v4.u32 [%0], {%1,%2,%3,%4};"
                 :: "l"(p), "r"(v.x), "r"(v.y), "r"(v.z), "r"(v.w) : "memory");
}
__device__ __forceinline__ void stg_cs_f1(float* p, float x) {
    asm volatile("st.global.cs.f32 [%0], %1;" :: "l"(p), "f"(x) : "memory");
}
#define CP_COMMIT() asm volatile("cp.async.commit_group;" ::: "memory")
#define CP_WAIT2()  asm volatile("cp.async.wait_group 2;" ::: "memory")
#define CP_WAIT4()  asm volatile("cp.async.wait_group 4;" ::: "memory")

// ---------------------------------------------------------------------------
// Smem-staged converter (unchanged R15/R16).
// ---------------------------------------------------------------------------
__global__ void cvt_all_kernel(const float* __restrict__ Q,
                               const float* __restrict__ K,
                               const float* __restrict__ V) {
    __shared__ float sm[16][264];
    const int blk = blockIdx.x;
    const int tid = threadIdx.x;

    const float* src;
    if (blk < 2048)       src = Q + ((size_t)(blk >> 7) * L_ + (blk & 127) * 16) * D_;
    else if (blk < 4096)  src = K + ((size_t)((blk - 2048) >> 7) * L_ + ((blk - 2048) & 127) * 16) * D_;
    else                  src = V + ((size_t)((blk - 4096) >> 7) * L_ + ((blk - 4096) & 127) * 16) * D_;

    #pragma unroll
    for (int t = 0; t < 4; t++) {
        const int idx = tid + t * 256;
        const int r = idx >> 6, c4 = (idx & 63) * 4;
        *(float4*)&sm[r][c4] = *(const float4*)(src + (size_t)r * D_ + c4);
    }
    __syncthreads();

    if (blk < 2048) {
        const int b = blk >> 7, qt = blk & 127;
        #pragma unroll
        for (int t = 0; t < 2; t++) {
            const int q = tid + t * 256;
            const int kc = q >> 5, lane = q & 31;
            const int g = lane >> 2, qd = lane & 3;
            const int c = kc * 16 + qd * 2;
            uint4 o;
            o.x = pack_bf16x2(sm[g][c],         sm[g][c + 1]);
            o.y = pack_bf16x2(sm[g + 8][c],     sm[g + 8][c + 1]);
            o.z = pack_bf16x2(sm[g][c + 8],     sm[g][c + 9]);
            o.w = pack_bf16x2(sm[g + 8][c + 8], sm[g + 8][c + 9]);
            g_Qfr[((size_t)(b * 128 + qt) * 16 + kc) * 32 + lane] = o;
        }
    } else if (blk < 4096) {
        const int j = blk - 2048;
        const int b = j >> 7, blk16 = j & 127;
        #pragma unroll
        for (int t = 0; t < 4; t++) {
            const int q = tid + t * 256;
            const int ntl = q >> 9, kc = (q >> 5) & 15, lane = q & 31;
            const int g = lane >> 2, qd = lane & 3;
            const int r = ntl * 8 + g, c = kc * 16 + qd * 2;
            uint2 o;
            o.x = pack_bf16x2(sm[r][c],     sm[r][c + 1]);
            o.y = pack_bf16x2(sm[r][c + 8], sm[r][c + 9]);
            const int nt = blk16 * 2 + ntl;
            g_Kfr[((size_t)(b * 256 + nt) * 16 + kc) * 32 + lane] = o;
        }
    } else {
        const int j = blk - 4096;
        const int b = j >> 7, kc = j & 127;
        #pragma unroll
        for (int t = 0; t < 4; t++) {
            const int q = tid + t * 256;
            const int nt = q >> 5, lane = q & 31;
            const int g = lane >> 2, qd = lane & 3;
            const int col = nt * 8 + g, r0 = 2 * qd;
            uint2 o;
            o.x = pack_f16x2(sm[r0][col],     sm[r0 + 1][col]);
            o.y = pack_f16x2(sm[r0 + 8][col], sm[r0 + 9][col]);
            g_Vf[((size_t)(b * 128 + kc) * 32 + nt) * 32 + lane] = o;
        }
    }
}

// ---------------------------------------------------------------------------
// Kernel 1: E = fp16(exp(scale * Q K^T)) quads + partial row sums.
// 6-stage cp.async pipeline, streaming E stores. (unchanged R16)
// ---------------------------------------------------------------------------
#define QK_STAGE_U 4096
#define QK_NSTAGE  6

__global__ __launch_bounds__(256, 2)
void qk_exp_kernel(const int* __restrict__ if_draw) {
    extern __shared__ unsigned smem_u[];
    const unsigned sbase = (unsigned)__cvta_generic_to_shared(smem_u);

    const int b  = blockIdx.z;
    const int by = blockIdx.y;
    const int kx = blockIdx.x;
    const int q0 = by * 128;
    const int k0 = kx * 128;

    const int tid  = threadIdx.x;
    const int lane = tid & 31;
    const int wid  = tid >> 5;
    const int wmid = wid & 1;
    const int wnid = wid >> 1;
    const int g    = lane >> 2;
    const int qd   = lane & 3;

    float acc[4][4][4] = {};

    auto load_stage = [&](int ss, int kt16) {
        const unsigned qdst = sbase + (unsigned)ss * QK_STAGE_U * 4;
        const unsigned kdst = qdst + 2048 * 4;
        #pragma unroll
        for (int t = 0; t < 2; t++) {
            const int idx = tid + t * 256;
            {
                const int qtl = idx >> 6, rem = idx & 63;
                const uint4* src = g_Qfr + ((size_t)(b * 128 + (q0 >> 4) + qtl) * 512
                                            + kt16 * 32 + rem);
                cp_async16(qdst + (unsigned)idx * 16, src);
            }
            {
                const int ntl = idx >> 5, rem = idx & 31;
                const uint2* src = g_Kfr + ((size_t)(b * 256 + (k0 >> 3) + ntl) * 512
                                            + kt16 * 32 + rem * 2);
                cp_async16(kdst + (unsigned)idx * 16, src);
            }
        }
    };

    #pragma unroll
    for (int s = 0; s < QK_NSTAGE - 1; s++) {
        load_stage(s, s * 2);
        CP_COMMIT();
    }

    for (int i = 0; i < 8; i++) {
        CP_WAIT4();
        __syncthreads();
        if (i + QK_NSTAGE - 1 < 8) load_stage((i + QK_NSTAGE - 1) % QK_NSTAGE, (i + QK_NSTAGE - 1) * 2);
        CP_COMMIT();

        const unsigned* Qst = smem_u + (i % QK_NSTAGE) * QK_STAGE_U;
        const unsigned* Kst = Qst + 2048;

        #pragma unroll
        for (int ks = 0; ks < 2; ks++) {
            unsigned a[4][4], bb[4][2];
            #pragma unroll
            for (int mt = 0; mt < 4; mt++) {
                const uint4 q4 = *(const uint4*)(Qst + ((wmid * 4 + mt) * 2 + ks) * 128 + lane * 4);
                a[mt][0] = q4.x; a[mt][1] = q4.y; a[mt][2] = q4.z; a[mt][3] = q4.w;
            }
            #pragma unroll
            for (int nt = 0; nt < 4; nt++) {
                const uint2 k2 = *(const uint2*)(Kst + ((wnid * 4 + nt) * 2 + ks) * 64 + lane * 2);
                bb[nt][0] = k2.x; bb[nt][1] = k2.y;
            }
            #pragma unroll
            for (int mt = 0; mt < 4; mt++)
                #pragma unroll
                for (int nt = 0; nt < 4; nt++)
                    mma_bf16(acc[mt][nt], a[mt], bb[nt]);
        }
    }

    const float scale = (if_draw[0] != 0) ? (1.0f / 320.0f) : (1.0f / 16.0f);
    uint4* Eq = g_Ef + (size_t)(b * 16 + by) * 32768;

    #pragma unroll
    for (int mt = 0; mt < 4; mt++) {
        float slo = 0.f, shi = 0.f;
        const int r16 = wmid * 4 + mt;
        #pragma unroll
        for (int c = 0; c < 2; c++) {
            const int nt0 = 2 * c, nt1 = 2 * c + 1;
            float e00 = __expf(scale * acc[mt][nt0][0]);
            float e01 = __expf(scale * acc[mt][nt0][1]);
            float e02 = __expf(scale * acc[mt][nt0][2]);
            float e03 = __expf(scale * acc[mt][nt0][3]);
            float e10 = __expf(scale * acc[mt][nt1][0]);
            float e11 = __expf(scale * acc[mt][nt1][1]);
            float e12 = __expf(scale * acc[mt][nt1][2]);
            float e13 = __expf(scale * acc[mt][nt1][3]);
            slo += e00 + e01 + e10 + e11;
            shi += e02 + e03 + e12 + e13;
            uint4 q;
            q.x = pack_f16x2(e00, e01);
            q.y = pack_f16x2(e02, e03);
            q.z = pack_f16x2(e10, e11);
            q.w = pack_f16x2(e12, e13);
            const int kchunk = kx * 8 + wnid * 2 + c;
            stg_cs_u4(&Eq[(size_t)(r16 * 128 + kchunk) * 32 + lane], q);
        }
        slo += __shfl_xor_sync(0xffffffffu, slo, 1);
        slo += __shfl_xor_sync(0xffffffffu, slo, 2);
        shi += __shfl_xor_sync(0xffffffffu, shi, 1);
        shi += __shfl_xor_sync(0xffffffffu, shi, 2);
        if (qd == 0) {
            const size_t rbase = (size_t)(b * L_ + q0 + wmid * 64 + mt * 16 + g) * 64 + kx * 4 + wnid;
            stg_cs_f1(&g_part[rbase], slo);
            stg_cs_f1(&g_part[rbase + 8 * 64], shi);
        }
    }
}

// ---------------------------------------------------------------------------
// Kernel 2 (fp16 mma): O = (E @ V) * inv ; attn = fp32(E) * inv.
// HALF-PANEL CTAs: 64 rows x 256 cols, 256 threads (8 warps, warp tile 64x32),
// 2 CTAs/SM. 4-stage pipeline (stage = A 4KB + V 16KB).
// ---------------------------------------------------------------------------
#define AV_STAGE_B 20480
#define AV_NSTAGE  4

__global__ __launch_bounds__(256, 2)
void av_f16_kernel(float* __restrict__ O,
                   float* __restrict__ attn) {
    extern __shared__ unsigned char smem_raw[];
    const unsigned sbase = (unsigned)__cvta_generic_to_shared(smem_raw);
    float* inv_s = (float*)(smem_raw + AV_NSTAGE * AV_STAGE_B);   // 64 floats

    const int b  = blockIdx.y;
    const int qh = blockIdx.x;          // half-panel 0..31
    const int qp = qh >> 1;
    const int q0 = qh * 64;

    // E quads for this half-panel: 4 whole r16-blocks.
    const uint4* Ab = g_Ef + (size_t)(b * 16 + qp) * 32768
                           + (size_t)((qh & 1) * 4) * 4096;
    const unsigned char* Vb = (const unsigned char*)(g_Vf + (size_t)b * 131072);

    const int tid  = threadIdx.x;
    const int lane = tid & 31;
    const int wid  = tid >> 5;          // 0..7
    const int ntb  = wid * 4;           // ntile base (0..28)
    const int g    = lane >> 2;
    const int qd   = lane & 3;

    const int aw_r16 = tid >> 6;        // 0..3 (local r16)
    const int aw_kcl = (tid >> 5) & 1;
    const int aw_g   = (tid & 31) >> 2;
    const int aw_qd  = tid & 3;
    const int aw_odd = aw_qd & 1;
    const int aw_cb0 = aw_kcl * 16 + 4 * (aw_qd >> 1) + aw_odd * 8;

    float acc[4][4][4] = {};

    // Row-sum partial loads issued first (overlap the cp.async prologue).
    const int rs_row = tid >> 2, rs_q = tid & 3;   // 64 rows x 4 quarters
    float rs = 0.f;
    {
        const float* p = g_part + (size_t)(b * L_ + q0 + rs_row) * 64 + rs_q * 16;
        #pragma unroll
        for (int t = 0; t < 16; t += 4) {
            const float4 v = *(const float4*)(p + t);
            rs += (v.x + v.y) + (v.z + v.w);
        }
    }

    auto load_stage = [&](int ss, int i) {
        const unsigned adst = sbase + (unsigned)ss * AV_STAGE_B;
        const unsigned vdst = adst + 4096;
        {   // A: 256 quads, 1 per thread
            const int r16 = tid >> 6, kcl = (tid >> 5) & 1, ln = tid & 31;
            cp_async16(adst + (unsigned)tid * 16,
                       Ab + (size_t)r16 * 4096 + (2 * i + kcl) * 32 + ln);
        }
        #pragma unroll
        for (int t = 0; t < 4; t++) {   // V: 1024 chunks, 4 per thread
            const int idx = tid + t * 256;
            cp_async16(vdst + (unsigned)idx * 16, Vb + (size_t)i * 16384 + idx * 16);
        }
    };

    #pragma unroll
    for (int s = 0; s < AV_NSTAGE - 1; s++) {
        load_stage(s, s);
        CP_COMMIT();
    }

    // finish row-sum reduction
    rs += __shfl_xor_sync(0xffffffffu, rs, 1);
    rs += __shfl_xor_sync(0xffffffffu, rs, 2);
    if (rs_q == 0) inv_s[rs_row] = 1.0f / rs;

    float* attn_b = attn + (size_t)b * L_ * L_;

    for (int i = 0; i < 64; i++) {
        CP_WAIT2();
        __syncthreads();
        if (i + AV_NSTAGE - 1 < 64) load_stage((i + AV_NSTAGE - 1) & 3, i + AV_NSTAGE - 1);
        CP_COMMIT();

        const unsigned char* Ast = smem_raw + (i & 3) * AV_STAGE_B;
        const unsigned char* Vst = Ast + 4096;

        // mma first — tensor pipe gets issue priority at stage start.
        #pragma unroll
        for (int kc = 0; kc < 2; kc++) {
            unsigned a[4][4], bb[4][2];
            #pragma unroll
            for (int mt = 0; mt < 4; mt++) {
                const uint4 q4 = *(const uint4*)(Ast + ((mt * 2 + kc) * 32 + lane) * 16);
                a[mt][0] = q4.x; a[mt][1] = q4.y; a[mt][2] = q4.z; a[mt][3] = q4.w;
            }
            #pragma unroll
            for (int nt = 0; nt < 4; nt++) {
                const uint2 v2 = *(const uint2*)(Vst + (((kc * 32) + ntb + nt) * 32 + lane) * 8);
                bb[nt][0] = v2.x; bb[nt][1] = v2.y;
            }
            #pragma unroll
            for (int mt = 0; mt < 4; mt++)
                #pragma unroll
                for (int nt = 0; nt < 4; nt++)
                    mma_f16(acc[mt][nt], a[mt], bb[nt]);
        }

        // attn = fp32(E) * inv — lane-pair exchange -> two 16B streaming stores.
        {
            const uint4 q4 = *(const uint4*)(Ast + tid * 16);
            const unsigned px = __shfl_xor_sync(0xffffffffu, q4.x, 1);
            const unsigned py = __shfl_xor_sync(0xffffffffu, q4.y, 1);
            const unsigned pz = __shfl_xor_sync(0xffffffffu, q4.z, 1);
            const unsigned pw = __shfl_xor_sync(0xffffffffu, q4.w, 1);
            const unsigned r0a = aw_odd ? pz : q4.x;
            const unsigned r0b = aw_odd ? q4.z : px;
            const unsigned r1a = aw_odd ? pw : q4.y;
            const unsigned r1b = aw_odd ? q4.w : py;
            const int lr0 = aw_r16 * 16 + aw_g, lr1 = lr0 + 8;
            const float iv0 = inv_s[lr0], iv1 = inv_s[lr1];
            const int cb = i * 32 + aw_cb0;
            const float2 A0 = __half22float2(*(const __half2*)&r0a);
            const float2 B0 = __half22float2(*(const __half2*)&r0b);
            stg_cs_f4(attn_b + (size_t)(q0 + lr0) * L_ + cb,
                      A0.x * iv0, A0.y * iv0, B0.x * iv0, B0.y * iv0);
            const float2 A1 = __half22float2(*(const __half2*)&r1a);
            const float2 B1 = __half22float2(*(const __half2*)&r1b);
            stg_cs_f4(attn_b + (size_t)(q0 + lr1) * L_ + cb,
                      A1.x * iv1, A1.y * iv1, B1.x * iv1, B1.y * iv1);
        }
    }

    float* Ob = O + (size_t)b * L_ * D_;
    #pragma unroll
    for (int mt = 0; mt < 4; mt++) {
        const int lrow = mt * 16 + g;           // local row 0..63
        const int row  = q0 + lrow;
        const float iv0 = inv_s[lrow];
        const float iv1 = inv_s[lrow + 8];
        #pragma unroll
        for (int nt = 0; nt < 4; nt++) {
            const int col = (ntb + nt) * 8 + 2 * qd;
            stg_cs_f2(Ob + (size_t)row * D_ + col,
                      acc[mt][nt][0] * iv0, acc[mt][nt][1] * iv0);
            stg_cs_f2(Ob + (size_t)(row + 8) * D_ + col,
                      acc[mt][nt][2] * iv1, acc[mt][nt][3] * iv1);
        }
    }
}

// ---------------------------------------------------------------------------
// Launch
// ---------------------------------------------------------------------------
extern "C" void kernel_launch(void* const* d_in, const int* in_sizes, int n_in,
                              void* d_out, int out_size) {
    const float* Q = (const float*)d_in[0];
    const float* K = (const float*)d_in[1];
    const float* V = (const float*)d_in[2];
    const int* if_draw = (const int*)d_in[4];

    float* out = (float*)d_out;

    const long long ctx_elems  = (long long)B_ * L_ * D_;
    const long long attn_elems = (long long)B_ * L_ * L_;

    float* Sptr;
    if ((long long)out_size >= ctx_elems + attn_elems)
        Sptr = out + ((long long)out_size - attn_elems);
    else
        Sptr = out + ctx_elems;

    static int attr_done = 0;
    const int qk_smem = QK_STAGE_U * QK_NSTAGE * 4;      // 98304 B
    const int av_smem = AV_STAGE_B * AV_NSTAGE + 256;    // 82176 B
    if (!attr_done) {
        cudaFuncSetAttribute(qk_exp_kernel, cudaFuncAttributeMaxDynamicSharedMemorySize, qk_smem);
        cudaFuncSetAttribute(av_f16_kernel, cudaFuncAttributeMaxDynamicSharedMemorySize, av_smem);
        attr_done = 1;
    }

    cvt_all_kernel<<<6144, 256>>>(Q, K, V);

    dim3 g1(L_ / 128, L_ / 128, B_);
    qk_exp_kernel<<<g1, 256, qk_smem>>>(if_draw);

    dim3 g2(32, B_);                    // (half-panel, b)
    av_f16_kernel<<<g2, 256, av_smem>>>(out, Sptr);
}